// round 14
// baseline (speedup 1.0000x reference)
#include <cuda_runtime.h>
#include <math.h>
#include <stdint.h>

#define NS 1024
#define NQ 8192
#define DD 256
#define EPSR 0.05f
#define INV_EPS 20.0f
#define THRESHV 1e-3f
#define MAX_ITER 100
#define SPLITK 16
#define GRIDB 296          // 2 blocks per SM, uniform
#define TPB 512

// row partition: blocks [0,136) get 4 rows, [136,296) get 3  (136*4+160*3=1024)
#define R4_BLOCKS 136
// col4 partition: blocks [0,272) get 7 groups, [272,296) get 6 (272*7+24*6=2048)
#define C7_BLOCKS 272

// log2-domain scale: INV_EPS * log2(e)
#define K2   28.853900817779268f
#define LN2  0.6931471805599453f
#define LOG_MU  (-6.93146156565f)
#define LOG_NU  (-9.01083143063f)

// ---------------- device scratch ----------------
__device__ float g_C[(size_t)NS * NQ];
__device__ float g_u[NS];
__device__ float g_v[NQ];
__device__ float g_rowerr[NS];
__device__ float g_mu[NS];
__device__ float g_mv[NQ];
__device__ float g_m[NS];
__device__ float g_sinv[NS];
__device__ float g_x2[NS];
__device__ float g_y2[NQ];
__device__ float g_part[(size_t)SPLITK * NS * DD];
__device__ int   g_done;
__device__ int   g_dmax[2];
__device__ int   g_dmaxv[2];
__device__ unsigned          g_arrive;
__device__ volatile unsigned g_gen;

// ---------------- MUFU / tf32 helpers ----------------
__device__ __forceinline__ float ex2f(float x) {
    float r; asm("ex2.approx.f32 %0, %1;" : "=f"(r) : "f"(x)); return r;
}
__device__ __forceinline__ float lg2f(float x) {
    float r; asm("lg2.approx.f32 %0, %1;" : "=f"(r) : "f"(x)); return r;
}
__device__ __forceinline__ uint32_t tf32r(float x) {
    uint32_t u; asm("cvt.rna.tf32.f32 %0, %1;" : "=r"(u) : "f"(x)); return u;
}
__device__ __forceinline__ void mma_tf32(float* c,
    uint32_t a0, uint32_t a1, uint32_t a2, uint32_t a3,
    uint32_t b0, uint32_t b1) {
    asm volatile(
        "mma.sync.aligned.m16n8k8.row.col.f32.tf32.tf32.f32 "
        "{%0,%1,%2,%3},{%4,%5,%6,%7},{%8,%9},{%0,%1,%2,%3};\n"
        : "+f"(c[0]), "+f"(c[1]), "+f"(c[2]), "+f"(c[3])
        : "r"(a0), "r"(a1), "r"(a2), "r"(a3), "r"(b0), "r"(b1));
}

// ---------------- software grid barrier ----------------
__device__ __forceinline__ void grid_barrier(unsigned target) {
    __syncthreads();
    if (threadIdx.x == 0) {
        __threadfence();
        unsigned prev = atomicAdd(&g_arrive, 1u);
        if (prev == GRIDB - 1) {
            g_arrive = 0;
            __threadfence();
            g_gen = target;
        } else {
            int spins = 0;
            while (g_gen != target) {
                if (++spins > 64) __nanosleep(32);
            }
            __threadfence();
        }
    }
    __syncthreads();
}

// ---------------- init ----------------
__global__ void k_init() {
    int t = blockIdx.x * blockDim.x + threadIdx.x;
    if (t < NS) { g_u[t] = 0.0f; g_mu[t] = 0.0f; }
    if (t < NQ) { g_v[t] = 0.0f; g_mv[t] = 0.0f; }
    if (t == 0) {
        g_done = 0; g_arrive = 0; g_gen = 0;
        g_dmax[0] = 0; g_dmax[1] = 0; g_dmaxv[0] = 0; g_dmaxv[1] = 0;
    }
}

// ---------------- squared norms ----------------
__global__ void k_norms(const float* __restrict__ zs, const float* __restrict__ zq) {
    int warp = (blockIdx.x * blockDim.x + threadIdx.x) >> 5;
    int lane = threadIdx.x & 31;
    if (warp >= NS + NQ) return;
    const float* row;
    float* out;
    if (warp < NS) { row = zs + (size_t)warp * DD;        out = g_x2 + warp; }
    else           { row = zq + (size_t)(warp - NS) * DD; out = g_y2 + (warp - NS); }
    float s = 0.0f;
    #pragma unroll
    for (int k = lane; k < DD; k += 32) { float v = row[k]; s = fmaf(v, v, s); }
    #pragma unroll
    for (int off = 16; off; off >>= 1) s += __shfl_down_sync(0xffffffffu, s, off);
    if (lane == 0) *out = s;
}

// ---------------- cost matrix via tf32 mma (3-product split) ----------------
#define APAD 20
__global__ __launch_bounds__(256) void k_cost(const float* __restrict__ A,
                                              const float* __restrict__ B) {
    __shared__ float Ah[128][APAD], Al[128][APAD];
    __shared__ float Bh[128][APAD], Bl[128][APAD];
    int tid = threadIdx.x;
    int lane = tid & 31, wid = tid >> 5;
    int warp_m = (wid & 3) * 32, warp_n = (wid >> 2) * 64;
    int m0 = blockIdx.y * 128, n0 = blockIdx.x * 128;
    int gid = lane >> 2, tig = lane & 3;

    float acc[2][8][4];
    #pragma unroll
    for (int mi = 0; mi < 2; mi++)
        #pragma unroll
        for (int ni = 0; ni < 8; ni++)
            #pragma unroll
            for (int q = 0; q < 4; q++) acc[mi][ni][q] = 0.0f;

    for (int kk0 = 0; kk0 < DD; kk0 += 16) {
        #pragma unroll
        for (int q = 0; q < 2; q++) {
            int i = tid + q * 256;
            int row = i >> 2, f4 = i & 3;
            float4 a = *reinterpret_cast<const float4*>(A + (size_t)(m0 + row) * DD + kk0 + f4 * 4);
            float4 b = *reinterpret_cast<const float4*>(B + (size_t)(n0 + row) * DD + kk0 + f4 * 4);
            float4 hx, lx;
            hx.x = __uint_as_float(tf32r(a.x)); lx.x = __uint_as_float(tf32r(a.x - hx.x));
            hx.y = __uint_as_float(tf32r(a.y)); lx.y = __uint_as_float(tf32r(a.y - hx.y));
            hx.z = __uint_as_float(tf32r(a.z)); lx.z = __uint_as_float(tf32r(a.z - hx.z));
            hx.w = __uint_as_float(tf32r(a.w)); lx.w = __uint_as_float(tf32r(a.w - hx.w));
            *reinterpret_cast<float4*>(&Ah[row][f4 * 4]) = hx;
            *reinterpret_cast<float4*>(&Al[row][f4 * 4]) = lx;
            hx.x = __uint_as_float(tf32r(b.x)); lx.x = __uint_as_float(tf32r(b.x - hx.x));
            hx.y = __uint_as_float(tf32r(b.y)); lx.y = __uint_as_float(tf32r(b.y - hx.y));
            hx.z = __uint_as_float(tf32r(b.z)); lx.z = __uint_as_float(tf32r(b.z - hx.z));
            hx.w = __uint_as_float(tf32r(b.w)); lx.w = __uint_as_float(tf32r(b.w - hx.w));
            *reinterpret_cast<float4*>(&Bh[row][f4 * 4]) = hx;
            *reinterpret_cast<float4*>(&Bl[row][f4 * 4]) = lx;
        }
        __syncthreads();
        #pragma unroll
        for (int k8 = 0; k8 < 2; k8++) {
            int kc = k8 * 8 + tig;
            uint32_t ah[2][4], al[2][4];
            #pragma unroll
            for (int mi = 0; mi < 2; mi++) {
                int rb = warp_m + mi * 16 + gid;
                ah[mi][0] = __float_as_uint(Ah[rb][kc]);
                ah[mi][1] = __float_as_uint(Ah[rb + 8][kc]);
                ah[mi][2] = __float_as_uint(Ah[rb][kc + 4]);
                ah[mi][3] = __float_as_uint(Ah[rb + 8][kc + 4]);
                al[mi][0] = __float_as_uint(Al[rb][kc]);
                al[mi][1] = __float_as_uint(Al[rb + 8][kc]);
                al[mi][2] = __float_as_uint(Al[rb][kc + 4]);
                al[mi][3] = __float_as_uint(Al[rb + 8][kc + 4]);
            }
            #pragma unroll
            for (int ni = 0; ni < 8; ni++) {
                int nb = warp_n + ni * 8 + gid;
                uint32_t bh0 = __float_as_uint(Bh[nb][kc]);
                uint32_t bh1 = __float_as_uint(Bh[nb][kc + 4]);
                uint32_t bl0 = __float_as_uint(Bl[nb][kc]);
                uint32_t bl1 = __float_as_uint(Bl[nb][kc + 4]);
                #pragma unroll
                for (int mi = 0; mi < 2; mi++) {
                    mma_tf32(acc[mi][ni], ah[mi][0], ah[mi][1], ah[mi][2], ah[mi][3], bh0, bh1);
                    mma_tf32(acc[mi][ni], ah[mi][0], ah[mi][1], ah[mi][2], ah[mi][3], bl0, bl1);
                    mma_tf32(acc[mi][ni], al[mi][0], al[mi][1], al[mi][2], al[mi][3], bh0, bh1);
                }
            }
        }
        __syncthreads();
    }
    #pragma unroll
    for (int mi = 0; mi < 2; mi++) {
        int r0 = m0 + warp_m + mi * 16 + gid;
        float x2a = g_x2[r0], x2b = g_x2[r0 + 8];
        #pragma unroll
        for (int ni = 0; ni < 8; ni++) {
            int c0 = n0 + warp_n + ni * 8 + 2 * tig;
            float y20 = g_y2[c0], y21 = g_y2[c0 + 1];
            float2 w0 = { x2a + y20 - 2.0f * acc[mi][ni][0],
                          x2a + y21 - 2.0f * acc[mi][ni][1] };
            float2 w1 = { x2b + y20 - 2.0f * acc[mi][ni][2],
                          x2b + y21 - 2.0f * acc[mi][ni][3] };
            *reinterpret_cast<float2*>(g_C + (size_t)r0 * NQ + c0) = w0;
            *reinterpret_cast<float2*>(g_C + (size_t)(r0 + 8) * NQ + c0) = w1;
        }
    }
}

// ---------------- u-phase body, R rows streamed concurrently ----------------
template<int R>
__device__ __forceinline__ float u_phase_go(const float* C0, int i0, bool onepass_u,
        float dmv2, int tid, int lane, int w,
        float (*mrow)[17], float (*ssum)[17]) {
    float delta2 = 0.0f;
    if (onepass_u) {
        float me2[R], mx[R], sa[R], sb[R];
        #pragma unroll
        for (int r = 0; r < R; r++) {
            me2[r] = fmaf(g_mu[i0 + r], K2, dmv2);
            mx[r] = -1e30f; sa[r] = 0.0f; sb[r] = 0.0f;
        }
        #pragma unroll
        for (int k = 0; k < 4; k++) {
            int off = tid * 4 + k * 2048;
            float4 vv = *reinterpret_cast<const float4*>(g_v + off);
            #pragma unroll
            for (int r = 0; r < R; r++) {
                float4 c = *reinterpret_cast<const float4*>(C0 + (size_t)r * NQ + off);
                float a0 = vv.x - c.x, a1 = vv.y - c.y, a2 = vv.z - c.z, a3 = vv.w - c.w;
                mx[r] = fmaxf(mx[r], fmaxf(fmaxf(a0, a1), fmaxf(a2, a3)));
                sa[r] += ex2f(fmaf(a0, K2, -me2[r])) + ex2f(fmaf(a2, K2, -me2[r]));
                sb[r] += ex2f(fmaf(a1, K2, -me2[r])) + ex2f(fmaf(a3, K2, -me2[r]));
            }
        }
        #pragma unroll
        for (int r = 0; r < R; r++) {
            float m = mx[r], s = sa[r] + sb[r];
            #pragma unroll
            for (int off = 16; off; off >>= 1) {
                m = fmaxf(m, __shfl_xor_sync(0xffffffffu, m, off));
                s += __shfl_xor_sync(0xffffffffu, s, off);
            }
            if (lane == 0) { mrow[r][w] = m; ssum[r][w] = s; }
        }
        __syncthreads();
        if (tid < R) {
            int i = i0 + tid;
            float me2t = fmaf(g_mu[i], K2, dmv2);
            float mr = mrow[tid][0];
            float S  = ssum[tid][0];
            #pragma unroll
            for (int q = 1; q < 16; q++) { mr = fmaxf(mr, mrow[tid][q]); S += ssum[tid][q]; }
            float L    = LN2 * (me2t + lg2f(S));
            float unew = EPSR * (LOG_MU - L);
            float d    = fabsf(unew - g_u[i]);
            g_rowerr[i] = d;
            g_u[i]  = unew;
            g_mu[i] = mr;
            delta2 = d * K2;
        }
    } else {
        float mx[R];
        #pragma unroll
        for (int r = 0; r < R; r++) mx[r] = -1e30f;
        #pragma unroll
        for (int k = 0; k < 4; k++) {
            int off = tid * 4 + k * 2048;
            float4 vv = *reinterpret_cast<const float4*>(g_v + off);
            #pragma unroll
            for (int r = 0; r < R; r++) {
                float4 c = *reinterpret_cast<const float4*>(C0 + (size_t)r * NQ + off);
                mx[r] = fmaxf(mx[r], fmaxf(fmaxf(vv.x - c.x, vv.y - c.y),
                                           fmaxf(vv.z - c.z, vv.w - c.w)));
            }
        }
        #pragma unroll
        for (int r = 0; r < R; r++) {
            float m = mx[r];
            #pragma unroll
            for (int off = 16; off; off >>= 1)
                m = fmaxf(m, __shfl_xor_sync(0xffffffffu, m, off));
            if (lane == 0) mrow[r][w] = m;
        }
        __syncthreads();
        float rm2[R];
        #pragma unroll
        for (int r = 0; r < R; r++) {
            float mr = mrow[r][0];
            #pragma unroll
            for (int q = 1; q < 16; q++) mr = fmaxf(mr, mrow[r][q]);
            rm2[r] = mr * K2;
            if (tid == r) g_mu[i0 + r] = mr;
        }
        float sa[R], sb[R];
        #pragma unroll
        for (int r = 0; r < R; r++) { sa[r] = 0.0f; sb[r] = 0.0f; }
        #pragma unroll
        for (int k = 0; k < 4; k++) {
            int off = tid * 4 + k * 2048;
            float4 vv = *reinterpret_cast<const float4*>(g_v + off);
            #pragma unroll
            for (int r = 0; r < R; r++) {
                float4 c = *reinterpret_cast<const float4*>(C0 + (size_t)r * NQ + off);
                sa[r] += ex2f(fmaf(vv.x - c.x, K2, -rm2[r])) + ex2f(fmaf(vv.z - c.z, K2, -rm2[r]));
                sb[r] += ex2f(fmaf(vv.y - c.y, K2, -rm2[r])) + ex2f(fmaf(vv.w - c.w, K2, -rm2[r]));
            }
        }
        #pragma unroll
        for (int r = 0; r < R; r++) {
            float s = sa[r] + sb[r];
            #pragma unroll
            for (int off = 16; off; off >>= 1)
                s += __shfl_xor_sync(0xffffffffu, s, off);
            if (lane == 0) ssum[r][w] = s;
        }
        __syncthreads();
        if (tid < R) {
            int i = i0 + tid;
            float S = ssum[tid][0];
            #pragma unroll
            for (int q = 1; q < 16; q++) S += ssum[tid][q];
            float L    = LN2 * (rm2[tid] + lg2f(S));
            float unew = EPSR * (LOG_MU - L);
            float d    = fabsf(unew - g_u[i]);
            g_rowerr[i] = d;
            g_u[i] = unew;
            delta2 = d * K2;
        }
    }
    return delta2;
}

// ---------------- stats epilogue body, R rows ----------------
template<int R>
__device__ __forceinline__ void stats_go(const float* C0, int i0, int tid, int lane, int w,
        float (*mrow)[17], float (*ssum)[17]) {
    float mx[R];
    #pragma unroll
    for (int r = 0; r < R; r++) mx[r] = -1e30f;
    #pragma unroll
    for (int k = 0; k < 4; k++) {
        int off = tid * 4 + k * 2048;
        float4 vv = *reinterpret_cast<const float4*>(g_v + off);
        #pragma unroll
        for (int r = 0; r < R; r++) {
            float4 c = *reinterpret_cast<const float4*>(C0 + (size_t)r * NQ + off);
            mx[r] = fmaxf(mx[r], fmaxf(fmaxf(vv.x - c.x, vv.y - c.y),
                                       fmaxf(vv.z - c.z, vv.w - c.w)));
        }
    }
    #pragma unroll
    for (int r = 0; r < R; r++) {
        float m = mx[r];
        #pragma unroll
        for (int off = 16; off; off >>= 1)
            m = fmaxf(m, __shfl_xor_sync(0xffffffffu, m, off));
        if (lane == 0) mrow[r][w] = m;
    }
    __syncthreads();
    float rm2[R];
    #pragma unroll
    for (int r = 0; r < R; r++) {
        float mr = mrow[r][0];
        #pragma unroll
        for (int q = 1; q < 16; q++) mr = fmaxf(mr, mrow[r][q]);
        rm2[r] = mr * K2;
    }
    float sa[R], sb[R];
    #pragma unroll
    for (int r = 0; r < R; r++) { sa[r] = 0.0f; sb[r] = 0.0f; }
    #pragma unroll
    for (int k = 0; k < 4; k++) {
        int off = tid * 4 + k * 2048;
        float4 vv = *reinterpret_cast<const float4*>(g_v + off);
        #pragma unroll
        for (int r = 0; r < R; r++) {
            float4 c = *reinterpret_cast<const float4*>(C0 + (size_t)r * NQ + off);
            sa[r] += ex2f(fmaf(vv.x - c.x, K2, -rm2[r])) + ex2f(fmaf(vv.z - c.z, K2, -rm2[r]));
            sb[r] += ex2f(fmaf(vv.y - c.y, K2, -rm2[r])) + ex2f(fmaf(vv.w - c.w, K2, -rm2[r]));
        }
    }
    #pragma unroll
    for (int r = 0; r < R; r++) {
        float s = sa[r] + sb[r];
        #pragma unroll
        for (int off = 16; off; off >>= 1)
            s += __shfl_xor_sync(0xffffffffu, s, off);
        if (lane == 0) ssum[r][w] = s;
    }
    __syncthreads();
    if (tid < R) {
        int i = i0 + tid;
        float S = ssum[tid][0];
        #pragma unroll
        for (int q = 1; q < 16; q++) S += ssum[tid][q];
        g_m[i]    = rm2[tid];
        g_sinv[i] = 1.0f / S;
    }
}

// ---------------- persistent Sinkhorn loop (balanced 296x512) ----------------
__global__ __launch_bounds__(TPB, 2) void k_sink() {
    __shared__ float mrow[4][17];
    __shared__ float ssum[4][17];
    __shared__ float smv[64][33];
    __shared__ float ssv[64][33];
    __shared__ float smM[32];
    __shared__ float u2s[NS];
    __shared__ float sered[16];

    int tid  = threadIdx.x, bid = blockIdx.x;
    int lane = tid & 31,    w   = tid >> 5;
    unsigned bargen = 0;
    bool done = false;

    // static partitions
    bool four  = (bid < R4_BLOCKS);
    int i0     = four ? bid * 4 : R4_BLOCKS * 4 + (bid - R4_BLOCKS) * 3;
    const float* C0 = g_C + (size_t)i0 * NQ;
    bool seven = (bid < C7_BLOCKS);
    int ncol4  = seven ? 7 : 6;
    int col0   = (seven ? bid * 7 : C7_BLOCKS * 7 + (bid - C7_BLOCKS) * 6) * 4;
    int ncols  = ncol4 * 4;

    int cg = tid & 7;          // col4 group (active if < ncol4)
    int rg = tid >> 3;         // 64 row-groups of 16 rows
    int ib = rg * 16;
    int cb = cg * 4;
    bool vact = (cg < ncol4);
    int jc = col0 + cb;
    const float* Cp = g_C + jc;

    for (int it = 0; it < MAX_ITER; it++) {
        if (done) break;
        int par = it & 1;

        // ======== u phase ========
        float dmv2 = __int_as_float(g_dmaxv[1 - par]);
        bool onepass_u = (it > 0) && (dmv2 <= 20.0f);
        float delta2 = four ? u_phase_go<4>(C0, i0, onepass_u, dmv2, tid, lane, w, mrow, ssum)
                            : u_phase_go<3>(C0, i0, onepass_u, dmv2, tid, lane, w, mrow, ssum);
        if (w == 0) {
            #pragma unroll
            for (int off = 16; off; off >>= 1)
                delta2 = fmaxf(delta2, __shfl_xor_sync(0xffffffffu, delta2, off));
            if (lane == 0) atomicMax(&g_dmax[par], __float_as_int(delta2));
        }

        grid_barrier(++bargen);

        // ======== v phase ========
        {
            u2s[tid]       = g_u[tid]       * K2;
            u2s[tid + TPB] = g_u[tid + TPB] * K2;
            if (bid == 0 && tid == 0) { g_dmax[1 - par] = 0; g_dmaxv[1 - par] = 0; }
            __syncthreads();

            float dmaxu2 = __int_as_float(g_dmax[par]);
            bool onepass = (it > 0) && (dmaxu2 <= 40.0f);

            if (onepass) {
                if (vact) {
                    float4 mvp = *reinterpret_cast<const float4*>(g_mv + jc);
                    float me0 = mvp.x + dmaxu2, me1 = mvp.y + dmaxu2;
                    float me2 = mvp.z + dmaxu2, me3 = mvp.w + dmaxu2;
                    float mx0 = -1e30f, mx1 = -1e30f, mx2 = -1e30f, mx3 = -1e30f;
                    float s0 = 0, s1 = 0, s2 = 0, s3 = 0;
                    #pragma unroll
                    for (int ii = 0; ii < 16; ii++) {
                        int i = ib + ii;
                        float4 c = *reinterpret_cast<const float4*>(Cp + (size_t)i * NQ);
                        float u2 = u2s[i];
                        float a0 = fmaf(c.x, -K2, u2);
                        float a1 = fmaf(c.y, -K2, u2);
                        float a2 = fmaf(c.z, -K2, u2);
                        float a3 = fmaf(c.w, -K2, u2);
                        mx0 = fmaxf(mx0, a0); s0 += ex2f(a0 - me0);
                        mx1 = fmaxf(mx1, a1); s1 += ex2f(a1 - me1);
                        mx2 = fmaxf(mx2, a2); s2 += ex2f(a2 - me2);
                        mx3 = fmaxf(mx3, a3); s3 += ex2f(a3 - me3);
                    }
                    smv[rg][cb+0] = mx0; ssv[rg][cb+0] = s0;
                    smv[rg][cb+1] = mx1; ssv[rg][cb+1] = s1;
                    smv[rg][cb+2] = mx2; ssv[rg][cb+2] = s2;
                    smv[rg][cb+3] = mx3; ssv[rg][cb+3] = s3;
                }
                __syncthreads();
                if (tid < 32) {
                    float dv2 = 0.0f;
                    if (tid < ncols) {
                        int j = col0 + tid;
                        float M = smv[0][tid], S = ssv[0][tid];
                        #pragma unroll
                        for (int q = 1; q < 64; q++) {
                            M = fmaxf(M, smv[q][tid]);
                            S += ssv[q][tid];
                        }
                        float m_est = g_mv[j] + dmaxu2;
                        g_mv[j] = M;
                        float vold = g_v[j];
                        float vnew = EPSR * (LOG_NU - LN2 * (m_est + lg2f(S)));
                        g_v[j] = vnew;
                        dv2 = fabsf(vnew - vold) * K2;
                    }
                    #pragma unroll
                    for (int off = 16; off; off >>= 1)
                        dv2 = fmaxf(dv2, __shfl_xor_sync(0xffffffffu, dv2, off));
                    if (tid == 0) atomicMax(&g_dmaxv[par], __float_as_int(dv2));
                }
            } else {
                if (vact) {
                    float mx0 = -1e30f, mx1 = -1e30f, mx2 = -1e30f, mx3 = -1e30f;
                    #pragma unroll
                    for (int ii = 0; ii < 16; ii++) {
                        int i = ib + ii;
                        float4 c = *reinterpret_cast<const float4*>(Cp + (size_t)i * NQ);
                        float u2 = u2s[i];
                        mx0 = fmaxf(mx0, fmaf(c.x, -K2, u2));
                        mx1 = fmaxf(mx1, fmaf(c.y, -K2, u2));
                        mx2 = fmaxf(mx2, fmaf(c.z, -K2, u2));
                        mx3 = fmaxf(mx3, fmaf(c.w, -K2, u2));
                    }
                    smv[rg][cb+0] = mx0; smv[rg][cb+1] = mx1;
                    smv[rg][cb+2] = mx2; smv[rg][cb+3] = mx3;
                }
                __syncthreads();
                if (tid < 32 && tid < ncols) {
                    float M = smv[0][tid];
                    #pragma unroll
                    for (int q = 1; q < 64; q++) M = fmaxf(M, smv[q][tid]);
                    smM[tid] = M;
                }
                __syncthreads();
                if (vact) {
                    float M0 = smM[cb+0], M1 = smM[cb+1], M2 = smM[cb+2], M3 = smM[cb+3];
                    float s0 = 0, s1 = 0, s2 = 0, s3 = 0;
                    #pragma unroll
                    for (int ii = 0; ii < 16; ii++) {
                        int i = ib + ii;
                        float4 c = *reinterpret_cast<const float4*>(Cp + (size_t)i * NQ);
                        float u2 = u2s[i];
                        s0 += ex2f(fmaf(c.x, -K2, u2) - M0);
                        s1 += ex2f(fmaf(c.y, -K2, u2) - M1);
                        s2 += ex2f(fmaf(c.z, -K2, u2) - M2);
                        s3 += ex2f(fmaf(c.w, -K2, u2) - M3);
                    }
                    ssv[rg][cb+0] = s0; ssv[rg][cb+1] = s1;
                    ssv[rg][cb+2] = s2; ssv[rg][cb+3] = s3;
                }
                __syncthreads();
                if (tid < 32) {
                    float dv2 = 0.0f;
                    if (tid < ncols) {
                        int j = col0 + tid;
                        float S = ssv[0][tid];
                        #pragma unroll
                        for (int q = 1; q < 64; q++) S += ssv[q][tid];
                        float M = smM[tid];
                        g_mv[j] = M;
                        float vold = g_v[j];
                        float vnew = EPSR * (LOG_NU - LN2 * (M + lg2f(S)));
                        g_v[j] = vnew;
                        dv2 = fabsf(vnew - vold) * K2;
                    }
                    #pragma unroll
                    for (int off = 16; off; off >>= 1)
                        dv2 = fmaxf(dv2, __shfl_xor_sync(0xffffffffu, dv2, off));
                    if (tid == 0) atomicMax(&g_dmaxv[par], __float_as_int(dv2));
                }
            }

            // block 0: convergence check
            if (bid == 0) {
                float e = g_rowerr[tid] + g_rowerr[tid + TPB];
                #pragma unroll
                for (int off = 16; off; off >>= 1)
                    e += __shfl_down_sync(0xffffffffu, e, off);
                if (lane == 0) sered[w] = e;
                __syncthreads();
                if (tid == 0) {
                    float E = 0;
                    #pragma unroll
                    for (int q = 0; q < 16; q++) E += sered[q];
                    if (E < THRESHV) g_done = 1;
                }
            }
        }

        grid_barrier(++bargen);
        done = (*(volatile int*)&g_done) != 0;
    }

    // ======== fused stats epilogue (exact, final v) ========
    if (four) stats_go<4>(C0, i0, tid, lane, w, mrow, ssum);
    else      stats_go<3>(C0, i0, tid, lane, w, mrow, ssum);
}

// ---------------- out = unnormalized-softmax(C) @ zq via tf32 mma (sinv in reduce) ----------------
#define BPAD 132
__global__ __launch_bounds__(256) void k_out(const float* __restrict__ B) {
    __shared__ float Ah[128][APAD], Al[128][APAD];
    __shared__ float Bh[16][BPAD], Bl[16][BPAD];
    int tid = threadIdx.x;
    int lane = tid & 31, wid = tid >> 5;
    int warp_m = (wid & 3) * 32, warp_n = (wid >> 2) * 64;
    int m0 = blockIdx.y * 128, n0 = blockIdx.x * 128;
    int kbase = blockIdx.z * (NQ / SPLITK);
    int gid = lane >> 2, tig = lane & 3;

    float acc[2][8][4];
    #pragma unroll
    for (int mi = 0; mi < 2; mi++)
        #pragma unroll
        for (int ni = 0; ni < 8; ni++)
            #pragma unroll
            for (int q = 0; q < 4; q++) acc[mi][ni][q] = 0.0f;

    for (int kk0 = kbase; kk0 < kbase + NQ / SPLITK; kk0 += 16) {
        #pragma unroll
        for (int q = 0; q < 2; q++) {
            int i = tid + q * 256;
            int row = i >> 2, f4 = i & 3;
            int grow = m0 + row;
            float mi2 = g_m[grow];
            float4 c  = *reinterpret_cast<const float4*>(g_C + (size_t)grow * NQ + kk0 + f4 * 4);
            float4 vv = *reinterpret_cast<const float4*>(g_v + kk0 + f4 * 4);
            float4 wv;
            wv.x = ex2f(fmaf(vv.x - c.x, K2, -mi2));
            wv.y = ex2f(fmaf(vv.y - c.y, K2, -mi2));
            wv.z = ex2f(fmaf(vv.z - c.z, K2, -mi2));
            wv.w = ex2f(fmaf(vv.w - c.w, K2, -mi2));
            float4 hx, lx;
            hx.x = __uint_as_float(tf32r(wv.x)); lx.x = __uint_as_float(tf32r(wv.x - hx.x));
            hx.y = __uint_as_float(tf32r(wv.y)); lx.y = __uint_as_float(tf32r(wv.y - hx.y));
            hx.z = __uint_as_float(tf32r(wv.z)); lx.z = __uint_as_float(tf32r(wv.z - hx.z));
            hx.w = __uint_as_float(tf32r(wv.w)); lx.w = __uint_as_float(tf32r(wv.w - hx.w));
            *reinterpret_cast<float4*>(&Ah[row][f4 * 4]) = hx;
            *reinterpret_cast<float4*>(&Al[row][f4 * 4]) = lx;
        }
        #pragma unroll
        for (int q = 0; q < 2; q++) {
            int i = tid + q * 256;
            int krow = i >> 5, f4c = i & 31;
            float4 b = *reinterpret_cast<const float4*>(B + (size_t)(kk0 + krow) * DD + n0 + f4c * 4);
            float4 hx, lx;
            hx.x = __uint_as_float(tf32r(b.x)); lx.x = __uint_as_float(tf32r(b.x - hx.x));
            hx.y = __uint_as_float(tf32r(b.y)); lx.y = __uint_as_float(tf32r(b.y - hx.y));
            hx.z = __uint_as_float(tf32r(b.z)); lx.z = __uint_as_float(tf32r(b.z - hx.z));
            hx.w = __uint_as_float(tf32r(b.w)); lx.w = __uint_as_float(tf32r(b.w - hx.w));
            *reinterpret_cast<float4*>(&Bh[krow][f4c * 4]) = hx;
            *reinterpret_cast<float4*>(&Bl[krow][f4c * 4]) = lx;
        }
        __syncthreads();
        #pragma unroll
        for (int k8 = 0; k8 < 2; k8++) {
            int kc = k8 * 8 + tig;
            uint32_t ah[2][4], al[2][4];
            #pragma unroll
            for (int mi = 0; mi < 2; mi++) {
                int rb = warp_m + mi * 16 + gid;
                ah[mi][0] = __float_as_uint(Ah[rb][kc]);
                ah[mi][1] = __float_as_uint(Ah[rb + 8][kc]);
                ah[mi][2] = __float_as_uint(Ah[rb][kc + 4]);
                ah[mi][3] = __float_as_uint(Ah[rb + 8][kc + 4]);
                al[mi][0] = __float_as_uint(Al[rb][kc]);
                al[mi][1] = __float_as_uint(Al[rb + 8][kc]);
                al[mi][2] = __float_as_uint(Al[rb][kc + 4]);
                al[mi][3] = __float_as_uint(Al[rb + 8][kc + 4]);
            }
            #pragma unroll
            for (int ni = 0; ni < 8; ni++) {
                int nb = warp_n + ni * 8 + gid;
                uint32_t bh0 = __float_as_uint(Bh[k8 * 8 + tig][nb]);
                uint32_t bh1 = __float_as_uint(Bh[k8 * 8 + tig + 4][nb]);
                uint32_t bl0 = __float_as_uint(Bl[k8 * 8 + tig][nb]);
                uint32_t bl1 = __float_as_uint(Bl[k8 * 8 + tig + 4][nb]);
                #pragma unroll
                for (int mi = 0; mi < 2; mi++) {
                    mma_tf32(acc[mi][ni], ah[mi][0], ah[mi][1], ah[mi][2], ah[mi][3], bh0, bh1);
                    mma_tf32(acc[mi][ni], ah[mi][0], ah[mi][1], ah[mi][2], ah[mi][3], bl0, bl1);
                    mma_tf32(acc[mi][ni], al[mi][0], al[mi][1], al[mi][2], al[mi][3], bh0, bh1);
                }
            }
        }
        __syncthreads();
    }
    float* P = g_part + (size_t)blockIdx.z * NS * DD;
    #pragma unroll
    for (int mi = 0; mi < 2; mi++) {
        int r0 = m0 + warp_m + mi * 16 + gid;
        #pragma unroll
        for (int ni = 0; ni < 8; ni++) {
            int c0 = n0 + warp_n + ni * 8 + 2 * tig;
            float2 w0 = { acc[mi][ni][0], acc[mi][ni][1] };
            float2 w1 = { acc[mi][ni][2], acc[mi][ni][3] };
            *reinterpret_cast<float2*>(P + (size_t)r0 * DD + c0) = w0;
            *reinterpret_cast<float2*>(P + (size_t)(r0 + 8) * DD + c0) = w1;
        }
    }
}

// ---------------- fused: reduce split-K + normalize, and copy z_query ----------------
#define RED_BLOCKS (NS * DD / 256)                 // 1024
#define CPY_BLOCKS (NQ * DD / 4 / 256)             // 2048
__global__ void k_finish(const float* __restrict__ zq, float* __restrict__ out) {
    int b = blockIdx.x;
    if (b < RED_BLOCKS) {
        int t = b * blockDim.x + threadIdx.x;
        float s = 0.0f;
        #pragma unroll
        for (int q = 0; q < SPLITK; q++) s += g_part[(size_t)q * NS * DD + t];
        out[t] = s * g_sinv[t >> 8];
    } else {
        int t = (b - RED_BLOCKS) * blockDim.x + threadIdx.x;
        reinterpret_cast<float4*>(out + NS * DD)[t] =
            reinterpret_cast<const float4*>(zq)[t];
    }
}

// ---------------- launch ----------------
extern "C" void kernel_launch(void* const* d_in, const int* in_sizes, int n_in,
                              void* d_out, int out_size) {
    const float* zs = (const float*)d_in[0];
    const float* zq = (const float*)d_in[1];
    if (n_in >= 2 && in_sizes[0] == NQ * DD) {
        const float* t = zs; zs = zq; zq = t;
    }
    float* out = (float*)d_out;

    k_init<<<(NQ + 255) / 256, 256>>>();
    k_norms<<<(NS + NQ) / 8, 256>>>(zs, zq);
    k_cost<<<dim3(NQ / 128, NS / 128), 256>>>(zs, zq);
    k_sink<<<GRIDB, TPB>>>();
    k_out<<<dim3(DD / 128, NS / 128, SPLITK), 256>>>(zq);
    k_finish<<<RED_BLOCKS + CPY_BLOCKS, 256>>>(zq, out);
}

// round 15
// speedup vs baseline: 1.0574x; 1.0574x over previous
#include <cuda_runtime.h>
#include <math.h>
#include <stdint.h>

#define NS 1024
#define NQ 8192
#define DD 256
#define EPSR 0.05f
#define INV_EPS 20.0f
#define THRESHV 1e-3f
#define MAX_ITER 100
#define SPLITK 16
#define GRIDB 256
#define TPB 512

// log2-domain scale: INV_EPS * log2(e)
#define K2   28.853900817779268f
#define LN2  0.6931471805599453f
#define LOG_MU  (-6.93146156565f)
#define LOG_NU  (-9.01083143063f)

// ---------------- device scratch ----------------
__device__ float g_C[(size_t)NS * NQ];
__device__ float g_u[NS];
__device__ float g_v[NQ];
__device__ float g_rowerr[NS];
__device__ float g_mu[NS];
__device__ float g_mv[NQ];
__device__ float g_m[NS];
__device__ float g_sinv[NS];
__device__ float g_x2[NS];
__device__ float g_y2[NQ];
__device__ float g_part[(size_t)SPLITK * NS * DD];
__device__ int   g_done;
__device__ int   g_dmax[2];
__device__ int   g_dmaxv[2];
__device__ unsigned          g_arrive;
__device__ volatile unsigned g_gen;

// ---------------- MUFU / tf32 helpers ----------------
__device__ __forceinline__ float ex2f(float x) {
    float r; asm("ex2.approx.f32 %0, %1;" : "=f"(r) : "f"(x)); return r;
}
__device__ __forceinline__ float lg2f(float x) {
    float r; asm("lg2.approx.f32 %0, %1;" : "=f"(r) : "f"(x)); return r;
}
__device__ __forceinline__ uint32_t tf32r(float x) {
    uint32_t u; asm("cvt.rna.tf32.f32 %0, %1;" : "=r"(u) : "f"(x)); return u;
}
__device__ __forceinline__ void mma_tf32(float* c,
    uint32_t a0, uint32_t a1, uint32_t a2, uint32_t a3,
    uint32_t b0, uint32_t b1) {
    asm volatile(
        "mma.sync.aligned.m16n8k8.row.col.f32.tf32.tf32.f32 "
        "{%0,%1,%2,%3},{%4,%5,%6,%7},{%8,%9},{%0,%1,%2,%3};\n"
        : "+f"(c[0]), "+f"(c[1]), "+f"(c[2]), "+f"(c[3])
        : "r"(a0), "r"(a1), "r"(a2), "r"(a3), "r"(b0), "r"(b1));
}

// ---------------- software grid barrier ----------------
__device__ __forceinline__ void grid_barrier(unsigned target) {
    __syncthreads();
    if (threadIdx.x == 0) {
        __threadfence();
        unsigned prev = atomicAdd(&g_arrive, 1u);
        if (prev == GRIDB - 1) {
            g_arrive = 0;
            __threadfence();
            g_gen = target;
        } else {
            int spins = 0;
            while (g_gen != target) {
                if (++spins > 64) __nanosleep(32);
            }
            __threadfence();
        }
    }
    __syncthreads();
}

// ---------------- init ----------------
__global__ void k_init() {
    int t = blockIdx.x * blockDim.x + threadIdx.x;
    if (t < NS) { g_u[t] = 0.0f; g_mu[t] = 0.0f; }
    if (t < NQ) { g_v[t] = 0.0f; g_mv[t] = 0.0f; }
    if (t == 0) {
        g_done = 0; g_arrive = 0; g_gen = 0;
        g_dmax[0] = 0; g_dmax[1] = 0; g_dmaxv[0] = 0; g_dmaxv[1] = 0;
    }
}

// ---------------- squared norms ----------------
__global__ void k_norms(const float* __restrict__ zs, const float* __restrict__ zq) {
    int warp = (blockIdx.x * blockDim.x + threadIdx.x) >> 5;
    int lane = threadIdx.x & 31;
    if (warp >= NS + NQ) return;
    const float* row;
    float* out;
    if (warp < NS) { row = zs + (size_t)warp * DD;        out = g_x2 + warp; }
    else           { row = zq + (size_t)(warp - NS) * DD; out = g_y2 + (warp - NS); }
    float s = 0.0f;
    #pragma unroll
    for (int k = lane; k < DD; k += 32) { float v = row[k]; s = fmaf(v, v, s); }
    #pragma unroll
    for (int off = 16; off; off >>= 1) s += __shfl_down_sync(0xffffffffu, s, off);
    if (lane == 0) *out = s;
}

// ---------------- cost matrix via tf32 mma (3-product split) ----------------
#define APAD 20
__global__ __launch_bounds__(256) void k_cost(const float* __restrict__ A,
                                              const float* __restrict__ B) {
    __shared__ float Ah[128][APAD], Al[128][APAD];
    __shared__ float Bh[128][APAD], Bl[128][APAD];
    int tid = threadIdx.x;
    int lane = tid & 31, wid = tid >> 5;
    int warp_m = (wid & 3) * 32, warp_n = (wid >> 2) * 64;
    int m0 = blockIdx.y * 128, n0 = blockIdx.x * 128;
    int gid = lane >> 2, tig = lane & 3;

    float acc[2][8][4];
    #pragma unroll
    for (int mi = 0; mi < 2; mi++)
        #pragma unroll
        for (int ni = 0; ni < 8; ni++)
            #pragma unroll
            for (int q = 0; q < 4; q++) acc[mi][ni][q] = 0.0f;

    for (int kk0 = 0; kk0 < DD; kk0 += 16) {
        #pragma unroll
        for (int q = 0; q < 2; q++) {
            int i = tid + q * 256;
            int row = i >> 2, f4 = i & 3;
            float4 a = *reinterpret_cast<const float4*>(A + (size_t)(m0 + row) * DD + kk0 + f4 * 4);
            float4 b = *reinterpret_cast<const float4*>(B + (size_t)(n0 + row) * DD + kk0 + f4 * 4);
            float4 hx, lx;
            hx.x = __uint_as_float(tf32r(a.x)); lx.x = __uint_as_float(tf32r(a.x - hx.x));
            hx.y = __uint_as_float(tf32r(a.y)); lx.y = __uint_as_float(tf32r(a.y - hx.y));
            hx.z = __uint_as_float(tf32r(a.z)); lx.z = __uint_as_float(tf32r(a.z - hx.z));
            hx.w = __uint_as_float(tf32r(a.w)); lx.w = __uint_as_float(tf32r(a.w - hx.w));
            *reinterpret_cast<float4*>(&Ah[row][f4 * 4]) = hx;
            *reinterpret_cast<float4*>(&Al[row][f4 * 4]) = lx;
            hx.x = __uint_as_float(tf32r(b.x)); lx.x = __uint_as_float(tf32r(b.x - hx.x));
            hx.y = __uint_as_float(tf32r(b.y)); lx.y = __uint_as_float(tf32r(b.y - hx.y));
            hx.z = __uint_as_float(tf32r(b.z)); lx.z = __uint_as_float(tf32r(b.z - hx.z));
            hx.w = __uint_as_float(tf32r(b.w)); lx.w = __uint_as_float(tf32r(b.w - hx.w));
            *reinterpret_cast<float4*>(&Bh[row][f4 * 4]) = hx;
            *reinterpret_cast<float4*>(&Bl[row][f4 * 4]) = lx;
        }
        __syncthreads();
        #pragma unroll
        for (int k8 = 0; k8 < 2; k8++) {
            int kc = k8 * 8 + tig;
            uint32_t ah[2][4], al[2][4];
            #pragma unroll
            for (int mi = 0; mi < 2; mi++) {
                int rb = warp_m + mi * 16 + gid;
                ah[mi][0] = __float_as_uint(Ah[rb][kc]);
                ah[mi][1] = __float_as_uint(Ah[rb + 8][kc]);
                ah[mi][2] = __float_as_uint(Ah[rb][kc + 4]);
                ah[mi][3] = __float_as_uint(Ah[rb + 8][kc + 4]);
                al[mi][0] = __float_as_uint(Al[rb][kc]);
                al[mi][1] = __float_as_uint(Al[rb + 8][kc]);
                al[mi][2] = __float_as_uint(Al[rb][kc + 4]);
                al[mi][3] = __float_as_uint(Al[rb + 8][kc + 4]);
            }
            #pragma unroll
            for (int ni = 0; ni < 8; ni++) {
                int nb = warp_n + ni * 8 + gid;
                uint32_t bh0 = __float_as_uint(Bh[nb][kc]);
                uint32_t bh1 = __float_as_uint(Bh[nb][kc + 4]);
                uint32_t bl0 = __float_as_uint(Bl[nb][kc]);
                uint32_t bl1 = __float_as_uint(Bl[nb][kc + 4]);
                #pragma unroll
                for (int mi = 0; mi < 2; mi++) {
                    mma_tf32(acc[mi][ni], ah[mi][0], ah[mi][1], ah[mi][2], ah[mi][3], bh0, bh1);
                    mma_tf32(acc[mi][ni], ah[mi][0], ah[mi][1], ah[mi][2], ah[mi][3], bl0, bl1);
                    mma_tf32(acc[mi][ni], al[mi][0], al[mi][1], al[mi][2], al[mi][3], bh0, bh1);
                }
            }
        }
        __syncthreads();
    }
    #pragma unroll
    for (int mi = 0; mi < 2; mi++) {
        int r0 = m0 + warp_m + mi * 16 + gid;
        float x2a = g_x2[r0], x2b = g_x2[r0 + 8];
        #pragma unroll
        for (int ni = 0; ni < 8; ni++) {
            int c0 = n0 + warp_n + ni * 8 + 2 * tig;
            float y20 = g_y2[c0], y21 = g_y2[c0 + 1];
            float2 w0 = { x2a + y20 - 2.0f * acc[mi][ni][0],
                          x2a + y21 - 2.0f * acc[mi][ni][1] };
            float2 w1 = { x2b + y20 - 2.0f * acc[mi][ni][2],
                          x2b + y21 - 2.0f * acc[mi][ni][3] };
            *reinterpret_cast<float2*>(g_C + (size_t)r0 * NQ + c0) = w0;
            *reinterpret_cast<float2*>(g_C + (size_t)(r0 + 8) * NQ + c0) = w1;
        }
    }
}

// ---------------- persistent Sinkhorn loop + fused stats epilogue ----------------
// rows i0,i0+1 cached in dynamic smem (64 KB); rows i0+2,i0+3 stream from L2
extern __shared__ float s_cache[];   // 2 * NQ floats

__global__ __launch_bounds__(TPB, 2) void k_sink() {
    __shared__ float mrow[4][17];
    __shared__ float ssum[4][17];
    __shared__ float smv[64][33];
    __shared__ float ssv[64][33];
    __shared__ float smM[32];
    __shared__ float u2s[NS];
    __shared__ float sered[16];

    int tid  = threadIdx.x, bid = blockIdx.x;
    int lane = tid & 31,    w   = tid >> 5;
    unsigned bargen = 0;
    bool done = false;
    int i0 = bid * 4;
    const float* C0 = g_C + (size_t)i0 * NQ;

    // preload rows i0, i0+1 into smem (once; C is constant during the loop)
    #pragma unroll
    for (int t = 0; t < (2 * NQ / 4) / TPB; t++) {
        int idx = tid + t * TPB;
        reinterpret_cast<float4*>(s_cache)[idx] =
            reinterpret_cast<const float4*>(C0)[idx];
    }
    __syncthreads();

    for (int it = 0; it < MAX_ITER; it++) {
        if (done) break;
        int par = it & 1;

        float dmv2 = __int_as_float(g_dmaxv[1 - par]);
        bool onepass_u = (it > 0) && (dmv2 <= 20.0f);

        if (onepass_u) {
            float me2_0 = fmaf(g_mu[i0+0], K2, dmv2);
            float me2_1 = fmaf(g_mu[i0+1], K2, dmv2);
            float me2_2 = fmaf(g_mu[i0+2], K2, dmv2);
            float me2_3 = fmaf(g_mu[i0+3], K2, dmv2);
            float mx[4] = {-1e30f, -1e30f, -1e30f, -1e30f};
            float ss[4] = {0, 0, 0, 0};
            #pragma unroll
            for (int k = 0; k < 4; k++) {
                int off = tid * 4 + k * 2048;
                float4 vv = *reinterpret_cast<const float4*>(g_v + off);
                float4 c0 = *reinterpret_cast<const float4*>(s_cache + off);
                float4 c1 = *reinterpret_cast<const float4*>(s_cache + NQ + off);
                float4 c2 = *reinterpret_cast<const float4*>(C0 + 2 * NQ + off);
                float4 c3 = *reinterpret_cast<const float4*>(C0 + 3 * NQ + off);
                {
                    float a0 = vv.x - c0.x, a1 = vv.y - c0.y, a2 = vv.z - c0.z, a3 = vv.w - c0.w;
                    mx[0] = fmaxf(mx[0], fmaxf(fmaxf(a0, a1), fmaxf(a2, a3)));
                    ss[0] += (ex2f(fmaf(a0, K2, -me2_0)) + ex2f(fmaf(a1, K2, -me2_0)))
                           + (ex2f(fmaf(a2, K2, -me2_0)) + ex2f(fmaf(a3, K2, -me2_0)));
                }
                {
                    float a0 = vv.x - c1.x, a1 = vv.y - c1.y, a2 = vv.z - c1.z, a3 = vv.w - c1.w;
                    mx[1] = fmaxf(mx[1], fmaxf(fmaxf(a0, a1), fmaxf(a2, a3)));
                    ss[1] += (ex2f(fmaf(a0, K2, -me2_1)) + ex2f(fmaf(a1, K2, -me2_1)))
                           + (ex2f(fmaf(a2, K2, -me2_1)) + ex2f(fmaf(a3, K2, -me2_1)));
                }
                {
                    float a0 = vv.x - c2.x, a1 = vv.y - c2.y, a2 = vv.z - c2.z, a3 = vv.w - c2.w;
                    mx[2] = fmaxf(mx[2], fmaxf(fmaxf(a0, a1), fmaxf(a2, a3)));
                    ss[2] += (ex2f(fmaf(a0, K2, -me2_2)) + ex2f(fmaf(a1, K2, -me2_2)))
                           + (ex2f(fmaf(a2, K2, -me2_2)) + ex2f(fmaf(a3, K2, -me2_2)));
                }
                {
                    float a0 = vv.x - c3.x, a1 = vv.y - c3.y, a2 = vv.z - c3.z, a3 = vv.w - c3.w;
                    mx[3] = fmaxf(mx[3], fmaxf(fmaxf(a0, a1), fmaxf(a2, a3)));
                    ss[3] += (ex2f(fmaf(a0, K2, -me2_3)) + ex2f(fmaf(a1, K2, -me2_3)))
                           + (ex2f(fmaf(a2, K2, -me2_3)) + ex2f(fmaf(a3, K2, -me2_3)));
                }
            }
            #pragma unroll
            for (int r = 0; r < 4; r++) {
                float m = mx[r], s = ss[r];
                #pragma unroll
                for (int off = 16; off; off >>= 1) {
                    m = fmaxf(m, __shfl_xor_sync(0xffffffffu, m, off));
                    s += __shfl_xor_sync(0xffffffffu, s, off);
                }
                if (lane == 0) { mrow[r][w] = m; ssum[r][w] = s; }
            }
            __syncthreads();
            float delta2 = 0.0f;
            if (tid < 4) {
                int i = i0 + tid;
                float me2 = fmaf(g_mu[i], K2, dmv2);
                float mr = mrow[tid][0];
                float S  = ssum[tid][0];
                #pragma unroll
                for (int q = 1; q < 16; q++) { mr = fmaxf(mr, mrow[tid][q]); S += ssum[tid][q]; }
                float L    = LN2 * (me2 + lg2f(S));
                float unew = EPSR * (LOG_MU - L);
                float d    = fabsf(unew - g_u[i]);
                g_rowerr[i] = d;
                g_u[i]  = unew;
                g_mu[i] = mr;
                delta2 = d * K2;
            }
            if (w == 0) {
                #pragma unroll
                for (int off = 16; off; off >>= 1)
                    delta2 = fmaxf(delta2, __shfl_xor_sync(0xffffffffu, delta2, off));
                if (lane == 0) atomicMax(&g_dmax[par], __float_as_int(delta2));
            }
        } else {
            float mx[4] = {-1e30f, -1e30f, -1e30f, -1e30f};
            #pragma unroll
            for (int k = 0; k < 4; k++) {
                int off = tid * 4 + k * 2048;
                float4 vv = *reinterpret_cast<const float4*>(g_v + off);
                float4 c0 = *reinterpret_cast<const float4*>(s_cache + off);
                float4 c1 = *reinterpret_cast<const float4*>(s_cache + NQ + off);
                float4 c2 = *reinterpret_cast<const float4*>(C0 + 2 * NQ + off);
                float4 c3 = *reinterpret_cast<const float4*>(C0 + 3 * NQ + off);
                mx[0] = fmaxf(mx[0], fmaxf(fmaxf(vv.x - c0.x, vv.y - c0.y),
                                           fmaxf(vv.z - c0.z, vv.w - c0.w)));
                mx[1] = fmaxf(mx[1], fmaxf(fmaxf(vv.x - c1.x, vv.y - c1.y),
                                           fmaxf(vv.z - c1.z, vv.w - c1.w)));
                mx[2] = fmaxf(mx[2], fmaxf(fmaxf(vv.x - c2.x, vv.y - c2.y),
                                           fmaxf(vv.z - c2.z, vv.w - c2.w)));
                mx[3] = fmaxf(mx[3], fmaxf(fmaxf(vv.x - c3.x, vv.y - c3.y),
                                           fmaxf(vv.z - c3.z, vv.w - c3.w)));
            }
            #pragma unroll
            for (int r = 0; r < 4; r++) {
                float m = mx[r];
                #pragma unroll
                for (int off = 16; off; off >>= 1)
                    m = fmaxf(m, __shfl_xor_sync(0xffffffffu, m, off));
                if (lane == 0) mrow[r][w] = m;
            }
            __syncthreads();
            float rm2[4];
            #pragma unroll
            for (int r = 0; r < 4; r++) {
                float mr = mrow[r][0];
                #pragma unroll
                for (int q = 1; q < 16; q++) mr = fmaxf(mr, mrow[r][q]);
                rm2[r] = mr * K2;
                if (tid == r) g_mu[i0 + r] = mr;
            }
            float ss[4] = {0, 0, 0, 0};
            #pragma unroll
            for (int k = 0; k < 4; k++) {
                int off = tid * 4 + k * 2048;
                float4 vv = *reinterpret_cast<const float4*>(g_v + off);
                float4 c0 = *reinterpret_cast<const float4*>(s_cache + off);
                float4 c1 = *reinterpret_cast<const float4*>(s_cache + NQ + off);
                float4 c2 = *reinterpret_cast<const float4*>(C0 + 2 * NQ + off);
                float4 c3 = *reinterpret_cast<const float4*>(C0 + 3 * NQ + off);
                ss[0] += (ex2f(fmaf(vv.x - c0.x, K2, -rm2[0])) + ex2f(fmaf(vv.y - c0.y, K2, -rm2[0])))
                       + (ex2f(fmaf(vv.z - c0.z, K2, -rm2[0])) + ex2f(fmaf(vv.w - c0.w, K2, -rm2[0])));
                ss[1] += (ex2f(fmaf(vv.x - c1.x, K2, -rm2[1])) + ex2f(fmaf(vv.y - c1.y, K2, -rm2[1])))
                       + (ex2f(fmaf(vv.z - c1.z, K2, -rm2[1])) + ex2f(fmaf(vv.w - c1.w, K2, -rm2[1])));
                ss[2] += (ex2f(fmaf(vv.x - c2.x, K2, -rm2[2])) + ex2f(fmaf(vv.y - c2.y, K2, -rm2[2])))
                       + (ex2f(fmaf(vv.z - c2.z, K2, -rm2[2])) + ex2f(fmaf(vv.w - c2.w, K2, -rm2[2])));
                ss[3] += (ex2f(fmaf(vv.x - c3.x, K2, -rm2[3])) + ex2f(fmaf(vv.y - c3.y, K2, -rm2[3])))
                       + (ex2f(fmaf(vv.z - c3.z, K2, -rm2[3])) + ex2f(fmaf(vv.w - c3.w, K2, -rm2[3])));
            }
            #pragma unroll
            for (int r = 0; r < 4; r++) {
                float s = ss[r];
                #pragma unroll
                for (int off = 16; off; off >>= 1)
                    s += __shfl_xor_sync(0xffffffffu, s, off);
                if (lane == 0) ssum[r][w] = s;
            }
            __syncthreads();
            float delta2 = 0.0f;
            if (tid < 4) {
                int i = i0 + tid;
                float S = ssum[tid][0];
                #pragma unroll
                for (int q = 1; q < 16; q++) S += ssum[tid][q];
                float L    = LN2 * (rm2[tid] + lg2f(S));
                float unew = EPSR * (LOG_MU - L);
                float d    = fabsf(unew - g_u[i]);
                g_rowerr[i] = d;
                g_u[i] = unew;
                delta2 = d * K2;
            }
            if (w == 0) {
                #pragma unroll
                for (int off = 16; off; off >>= 1)
                    delta2 = fmaxf(delta2, __shfl_xor_sync(0xffffffffu, delta2, off));
                if (lane == 0) atomicMax(&g_dmax[par], __float_as_int(delta2));
            }
        }

        grid_barrier(++bargen);

        {
            u2s[tid]       = g_u[tid]       * K2;
            u2s[tid + TPB] = g_u[tid + TPB] * K2;
            if (bid == 0 && tid == 0) { g_dmax[1 - par] = 0; g_dmaxv[1 - par] = 0; }
            __syncthreads();

            float dmaxu2 = __int_as_float(g_dmax[par]);
            bool onepass = (it > 0) && (dmaxu2 <= 40.0f);

            int cg = tid & 7;
            int rg = tid >> 3;
            int jc = bid * 32 + cg * 4;
            const float* Cp = g_C + jc;
            int ib = rg * 16;

            if (onepass) {
                float4 mvp = *reinterpret_cast<const float4*>(g_mv + jc);
                float me0 = mvp.x + dmaxu2, me1 = mvp.y + dmaxu2;
                float me2 = mvp.z + dmaxu2, me3 = mvp.w + dmaxu2;
                float mx0 = -1e30f, mx1 = -1e30f, mx2 = -1e30f, mx3 = -1e30f;
                float s0 = 0, s1 = 0, s2 = 0, s3 = 0;
                #pragma unroll
                for (int ii = 0; ii < 16; ii++) {
                    int i = ib + ii;
                    float4 c = *reinterpret_cast<const float4*>(Cp + (size_t)i * NQ);
                    float u2 = u2s[i];
                    float a0 = fmaf(c.x, -K2, u2);
                    float a1 = fmaf(c.y, -K2, u2);
                    float a2 = fmaf(c.z, -K2, u2);
                    float a3 = fmaf(c.w, -K2, u2);
                    mx0 = fmaxf(mx0, a0); s0 += ex2f(a0 - me0);
                    mx1 = fmaxf(mx1, a1); s1 += ex2f(a1 - me1);
                    mx2 = fmaxf(mx2, a2); s2 += ex2f(a2 - me2);
                    mx3 = fmaxf(mx3, a3); s3 += ex2f(a3 - me3);
                }
                int cb = cg * 4;
                smv[rg][cb+0] = mx0; ssv[rg][cb+0] = s0;
                smv[rg][cb+1] = mx1; ssv[rg][cb+1] = s1;
                smv[rg][cb+2] = mx2; ssv[rg][cb+2] = s2;
                smv[rg][cb+3] = mx3; ssv[rg][cb+3] = s3;
                __syncthreads();
                if (tid < 32) {
                    int j = bid * 32 + tid;
                    float M = smv[0][tid], S = ssv[0][tid];
                    #pragma unroll
                    for (int q = 1; q < 64; q++) {
                        M = fmaxf(M, smv[q][tid]);
                        S += ssv[q][tid];
                    }
                    float m_est = g_mv[j] + dmaxu2;
                    g_mv[j] = M;
                    float vold = g_v[j];
                    float vnew = EPSR * (LOG_NU - LN2 * (m_est + lg2f(S)));
                    g_v[j] = vnew;
                    float dv2 = fabsf(vnew - vold) * K2;
                    #pragma unroll
                    for (int off = 16; off; off >>= 1)
                        dv2 = fmaxf(dv2, __shfl_xor_sync(0xffffffffu, dv2, off));
                    if (tid == 0) atomicMax(&g_dmaxv[par], __float_as_int(dv2));
                }
            } else {
                float mx0 = -1e30f, mx1 = -1e30f, mx2 = -1e30f, mx3 = -1e30f;
                #pragma unroll
                for (int ii = 0; ii < 16; ii++) {
                    int i = ib + ii;
                    float4 c = *reinterpret_cast<const float4*>(Cp + (size_t)i * NQ);
                    float u2 = u2s[i];
                    mx0 = fmaxf(mx0, fmaf(c.x, -K2, u2));
                    mx1 = fmaxf(mx1, fmaf(c.y, -K2, u2));
                    mx2 = fmaxf(mx2, fmaf(c.z, -K2, u2));
                    mx3 = fmaxf(mx3, fmaf(c.w, -K2, u2));
                }
                int cb = cg * 4;
                smv[rg][cb+0] = mx0; smv[rg][cb+1] = mx1;
                smv[rg][cb+2] = mx2; smv[rg][cb+3] = mx3;
                __syncthreads();
                if (tid < 32) {
                    float M = smv[0][tid];
                    #pragma unroll
                    for (int q = 1; q < 64; q++) M = fmaxf(M, smv[q][tid]);
                    smM[tid] = M;
                }
                __syncthreads();
                float M0 = smM[cb+0], M1 = smM[cb+1], M2 = smM[cb+2], M3 = smM[cb+3];
                float s0 = 0, s1 = 0, s2 = 0, s3 = 0;
                #pragma unroll
                for (int ii = 0; ii < 16; ii++) {
                    int i = ib + ii;
                    float4 c = *reinterpret_cast<const float4*>(Cp + (size_t)i * NQ);
                    float u2 = u2s[i];
                    s0 += ex2f(fmaf(c.x, -K2, u2) - M0);
                    s1 += ex2f(fmaf(c.y, -K2, u2) - M1);
                    s2 += ex2f(fmaf(c.z, -K2, u2) - M2);
                    s3 += ex2f(fmaf(c.w, -K2, u2) - M3);
                }
                ssv[rg][cb+0] = s0; ssv[rg][cb+1] = s1;
                ssv[rg][cb+2] = s2; ssv[rg][cb+3] = s3;
                __syncthreads();
                if (tid < 32) {
                    int j = bid * 32 + tid;
                    float S = ssv[0][tid];
                    #pragma unroll
                    for (int q = 1; q < 64; q++) S += ssv[q][tid];
                    float M = smM[tid];
                    g_mv[j] = M;
                    float vold = g_v[j];
                    float vnew = EPSR * (LOG_NU - LN2 * (M + lg2f(S)));
                    g_v[j] = vnew;
                    float dv2 = fabsf(vnew - vold) * K2;
                    #pragma unroll
                    for (int off = 16; off; off >>= 1)
                        dv2 = fmaxf(dv2, __shfl_xor_sync(0xffffffffu, dv2, off));
                    if (tid == 0) atomicMax(&g_dmaxv[par], __float_as_int(dv2));
                }
            }

            if (bid == 0) {
                float e = g_rowerr[tid] + g_rowerr[tid + TPB];
                #pragma unroll
                for (int off = 16; off; off >>= 1)
                    e += __shfl_down_sync(0xffffffffu, e, off);
                if (lane == 0) sered[w] = e;
                __syncthreads();
                if (tid == 0) {
                    float E = 0;
                    #pragma unroll
                    for (int q = 0; q < 16; q++) E += sered[q];
                    if (E < THRESHV) g_done = 1;
                }
            }
        }

        grid_barrier(++bargen);
        done = (*(volatile int*)&g_done) != 0;
    }

    // fused stats epilogue (exact, final v; rows 0,1 from smem)
    {
        float mx[4] = {-1e30f, -1e30f, -1e30f, -1e30f};
        #pragma unroll
        for (int k = 0; k < 4; k++) {
            int off = tid * 4 + k * 2048;
            float4 vv = *reinterpret_cast<const float4*>(g_v + off);
            float4 c0 = *reinterpret_cast<const float4*>(s_cache + off);
            float4 c1 = *reinterpret_cast<const float4*>(s_cache + NQ + off);
            float4 c2 = *reinterpret_cast<const float4*>(C0 + 2 * NQ + off);
            float4 c3 = *reinterpret_cast<const float4*>(C0 + 3 * NQ + off);
            mx[0] = fmaxf(mx[0], fmaxf(fmaxf(vv.x - c0.x, vv.y - c0.y),
                                       fmaxf(vv.z - c0.z, vv.w - c0.w)));
            mx[1] = fmaxf(mx[1], fmaxf(fmaxf(vv.x - c1.x, vv.y - c1.y),
                                       fmaxf(vv.z - c1.z, vv.w - c1.w)));
            mx[2] = fmaxf(mx[2], fmaxf(fmaxf(vv.x - c2.x, vv.y - c2.y),
                                       fmaxf(vv.z - c2.z, vv.w - c2.w)));
            mx[3] = fmaxf(mx[3], fmaxf(fmaxf(vv.x - c3.x, vv.y - c3.y),
                                       fmaxf(vv.z - c3.z, vv.w - c3.w)));
        }
        #pragma unroll
        for (int r = 0; r < 4; r++) {
            float m = mx[r];
            #pragma unroll
            for (int off = 16; off; off >>= 1)
                m = fmaxf(m, __shfl_xor_sync(0xffffffffu, m, off));
            if (lane == 0) mrow[r][w] = m;
        }
        __syncthreads();
        float rm2[4];
        #pragma unroll
        for (int r = 0; r < 4; r++) {
            float mr = mrow[r][0];
            #pragma unroll
            for (int q = 1; q < 16; q++) mr = fmaxf(mr, mrow[r][q]);
            rm2[r] = mr * K2;
        }
        float ss[4] = {0, 0, 0, 0};
        #pragma unroll
        for (int k = 0; k < 4; k++) {
            int off = tid * 4 + k * 2048;
            float4 vv = *reinterpret_cast<const float4*>(g_v + off);
            float4 c0 = *reinterpret_cast<const float4*>(s_cache + off);
            float4 c1 = *reinterpret_cast<const float4*>(s_cache + NQ + off);
            float4 c2 = *reinterpret_cast<const float4*>(C0 + 2 * NQ + off);
            float4 c3 = *reinterpret_cast<const float4*>(C0 + 3 * NQ + off);
            ss[0] += (ex2f(fmaf(vv.x - c0.x, K2, -rm2[0])) + ex2f(fmaf(vv.y - c0.y, K2, -rm2[0])))
                   + (ex2f(fmaf(vv.z - c0.z, K2, -rm2[0])) + ex2f(fmaf(vv.w - c0.w, K2, -rm2[0])));
            ss[1] += (ex2f(fmaf(vv.x - c1.x, K2, -rm2[1])) + ex2f(fmaf(vv.y - c1.y, K2, -rm2[1])))
                   + (ex2f(fmaf(vv.z - c1.z, K2, -rm2[1])) + ex2f(fmaf(vv.w - c1.w, K2, -rm2[1])));
            ss[2] += (ex2f(fmaf(vv.x - c2.x, K2, -rm2[2])) + ex2f(fmaf(vv.y - c2.y, K2, -rm2[2])))
                   + (ex2f(fmaf(vv.z - c2.z, K2, -rm2[2])) + ex2f(fmaf(vv.w - c2.w, K2, -rm2[2])));
            ss[3] += (ex2f(fmaf(vv.x - c3.x, K2, -rm2[3])) + ex2f(fmaf(vv.y - c3.y, K2, -rm2[3])))
                   + (ex2f(fmaf(vv.z - c3.z, K2, -rm2[3])) + ex2f(fmaf(vv.w - c3.w, K2, -rm2[3])));
        }
        #pragma unroll
        for (int r = 0; r < 4; r++) {
            float s = ss[r];
            #pragma unroll
            for (int off = 16; off; off >>= 1)
                s += __shfl_xor_sync(0xffffffffu, s, off);
            if (lane == 0) ssum[r][w] = s;
        }
        __syncthreads();
        if (tid < 4) {
            int i = i0 + tid;
            float S = ssum[tid][0];
            #pragma unroll
            for (int q = 1; q < 16; q++) S += ssum[tid][q];
            g_m[i]    = rm2[tid];
            g_sinv[i] = 1.0f / S;
        }
    }
}

// ---------------- out = unnormalized-softmax(C) @ zq via tf32 mma (sinv in reduce) ----------------
#define BPAD 132
__global__ __launch_bounds__(256) void k_out(const float* __restrict__ B) {
    __shared__ float Ah[128][APAD], Al[128][APAD];
    __shared__ float Bh[16][BPAD], Bl[16][BPAD];
    int tid = threadIdx.x;
    int lane = tid & 31, wid = tid >> 5;
    int warp_m = (wid & 3) * 32, warp_n = (wid >> 2) * 64;
    int m0 = blockIdx.y * 128, n0 = blockIdx.x * 128;
    int kbase = blockIdx.z * (NQ / SPLITK);
    int gid = lane >> 2, tig = lane & 3;

    float acc[2][8][4];
    #pragma unroll
    for (int mi = 0; mi < 2; mi++)
        #pragma unroll
        for (int ni = 0; ni < 8; ni++)
            #pragma unroll
            for (int q = 0; q < 4; q++) acc[mi][ni][q] = 0.0f;

    for (int kk0 = kbase; kk0 < kbase + NQ / SPLITK; kk0 += 16) {
        #pragma unroll
        for (int q = 0; q < 2; q++) {
            int i = tid + q * 256;
            int row = i >> 2, f4 = i & 3;
            int grow = m0 + row;
            float mi2 = g_m[grow];
            float4 c  = *reinterpret_cast<const float4*>(g_C + (size_t)grow * NQ + kk0 + f4 * 4);
            float4 vv = *reinterpret_cast<const float4*>(g_v + kk0 + f4 * 4);
            float4 wv;
            wv.x = ex2f(fmaf(vv.x - c.x, K2, -mi2));
            wv.y = ex2f(fmaf(vv.y - c.y, K2, -mi2));
            wv.z = ex2f(fmaf(vv.z - c.z, K2, -mi2));
            wv.w = ex2f(fmaf(vv.w - c.w, K2, -mi2));
            float4 hx, lx;
            hx.x = __uint_as_float(tf32r(wv.x)); lx.x = __uint_as_float(tf32r(wv.x - hx.x));
            hx.y = __uint_as_float(tf32r(wv.y)); lx.y = __uint_as_float(tf32r(wv.y - hx.y));
            hx.z = __uint_as_float(tf32r(wv.z)); lx.z = __uint_as_float(tf32r(wv.z - hx.z));
            hx.w = __uint_as_float(tf32r(wv.w)); lx.w = __uint_as_float(tf32r(wv.w - hx.w));
            *reinterpret_cast<float4*>(&Ah[row][f4 * 4]) = hx;
            *reinterpret_cast<float4*>(&Al[row][f4 * 4]) = lx;
        }
        #pragma unroll
        for (int q = 0; q < 2; q++) {
            int i = tid + q * 256;
            int krow = i >> 5, f4c = i & 31;
            float4 b = *reinterpret_cast<const float4*>(B + (size_t)(kk0 + krow) * DD + n0 + f4c * 4);
            float4 hx, lx;
            hx.x = __uint_as_float(tf32r(b.x)); lx.x = __uint_as_float(tf32r(b.x - hx.x));
            hx.y = __uint_as_float(tf32r(b.y)); lx.y = __uint_as_float(tf32r(b.y - hx.y));
            hx.z = __uint_as_float(tf32r(b.z)); lx.z = __uint_as_float(tf32r(b.z - hx.z));
            hx.w = __uint_as_float(tf32r(b.w)); lx.w = __uint_as_float(tf32r(b.w - hx.w));
            *reinterpret_cast<float4*>(&Bh[krow][f4c * 4]) = hx;
            *reinterpret_cast<float4*>(&Bl[krow][f4c * 4]) = lx;
        }
        __syncthreads();
        #pragma unroll
        for (int k8 = 0; k8 < 2; k8++) {
            int kc = k8 * 8 + tig;
            uint32_t ah[2][4], al[2][4];
            #pragma unroll
            for (int mi = 0; mi < 2; mi++) {
                int rb = warp_m + mi * 16 + gid;
                ah[mi][0] = __float_as_uint(Ah[rb][kc]);
                ah[mi][1] = __float_as_uint(Ah[rb + 8][kc]);
                ah[mi][2] = __float_as_uint(Ah[rb][kc + 4]);
                ah[mi][3] = __float_as_uint(Ah[rb + 8][kc + 4]);
                al[mi][0] = __float_as_uint(Al[rb][kc]);
                al[mi][1] = __float_as_uint(Al[rb + 8][kc]);
                al[mi][2] = __float_as_uint(Al[rb][kc + 4]);
                al[mi][3] = __float_as_uint(Al[rb + 8][kc + 4]);
            }
            #pragma unroll
            for (int ni = 0; ni < 8; ni++) {
                int nb = warp_n + ni * 8 + gid;
                uint32_t bh0 = __float_as_uint(Bh[k8 * 8 + tig][nb]);
                uint32_t bh1 = __float_as_uint(Bh[k8 * 8 + tig + 4][nb]);
                uint32_t bl0 = __float_as_uint(Bl[k8 * 8 + tig][nb]);
                uint32_t bl1 = __float_as_uint(Bl[k8 * 8 + tig + 4][nb]);
                #pragma unroll
                for (int mi = 0; mi < 2; mi++) {
                    mma_tf32(acc[mi][ni], ah[mi][0], ah[mi][1], ah[mi][2], ah[mi][3], bh0, bh1);
                    mma_tf32(acc[mi][ni], ah[mi][0], ah[mi][1], ah[mi][2], ah[mi][3], bl0, bl1);
                    mma_tf32(acc[mi][ni], al[mi][0], al[mi][1], al[mi][2], al[mi][3], bh0, bh1);
                }
            }
        }
        __syncthreads();
    }
    float* P = g_part + (size_t)blockIdx.z * NS * DD;
    #pragma unroll
    for (int mi = 0; mi < 2; mi++) {
        int r0 = m0 + warp_m + mi * 16 + gid;
        #pragma unroll
        for (int ni = 0; ni < 8; ni++) {
            int c0 = n0 + warp_n + ni * 8 + 2 * tig;
            float2 w0 = { acc[mi][ni][0], acc[mi][ni][1] };
            float2 w1 = { acc[mi][ni][2], acc[mi][ni][3] };
            *reinterpret_cast<float2*>(P + (size_t)r0 * DD + c0) = w0;
            *reinterpret_cast<float2*>(P + (size_t)(r0 + 8) * DD + c0) = w1;
        }
    }
}

// ---------------- fused: reduce split-K + normalize, and copy z_query ----------------
#define RED_BLOCKS (NS * DD / 256)                 // 1024
#define CPY_BLOCKS (NQ * DD / 4 / 256)             // 2048
__global__ void k_finish(const float* __restrict__ zq, float* __restrict__ out) {
    int b = blockIdx.x;
    if (b < RED_BLOCKS) {
        int t = b * blockDim.x + threadIdx.x;
        float s = 0.0f;
        #pragma unroll
        for (int q = 0; q < SPLITK; q++) s += g_part[(size_t)q * NS * DD + t];
        out[t] = s * g_sinv[t >> 8];
    } else {
        int t = (b - RED_BLOCKS) * blockDim.x + threadIdx.x;
        reinterpret_cast<float4*>(out + NS * DD)[t] =
            reinterpret_cast<const float4*>(zq)[t];
    }
}

// ---------------- launch ----------------
extern "C" void kernel_launch(void* const* d_in, const int* in_sizes, int n_in,
                              void* d_out, int out_size) {
    const float* zs = (const float*)d_in[0];
    const float* zq = (const float*)d_in[1];
    if (n_in >= 2 && in_sizes[0] == NQ * DD) {
        const float* t = zs; zs = zq; zq = t;
    }
    float* out = (float*)d_out;

    cudaFuncSetAttribute(k_sink, cudaFuncAttributeMaxDynamicSharedMemorySize,
                         2 * NQ * (int)sizeof(float));

    k_init<<<(NQ + 255) / 256, 256>>>();
    k_norms<<<(NS + NQ) / 8, 256>>>(zs, zq);
    k_cost<<<dim3(NQ / 128, NS / 128), 256>>>(zs, zq);
    k_sink<<<GRIDB, TPB, 2 * NQ * sizeof(float)>>>();
    k_out<<<dim3(DD / 128, NS / 128, SPLITK), 256>>>(zq);
    k_finish<<<RED_BLOCKS + CPY_BLOCKS, 256>>>(zq, out);
}

// round 16
// speedup vs baseline: 1.0759x; 1.0176x over previous
#include <cuda_runtime.h>
#include <math.h>
#include <stdint.h>

#define NS 1024
#define NQ 8192
#define DD 256
#define EPSR 0.05f
#define INV_EPS 20.0f
#define THRESHV 1e-3f
#define MAX_ITER 100
#define SPLITK 16
#define GRIDB 256
#define TPB 512

// log2-domain scale: INV_EPS * log2(e)
#define K2   28.853900817779268f
#define LN2  0.6931471805599453f
#define LOG_MU  (-6.93146156565f)
#define LOG_NU  (-9.01083143063f)

// ---------------- device scratch ----------------
__device__ float g_C[(size_t)NS * NQ];
__device__ float g_u[NS];
__device__ float g_v[NQ];
__device__ float g_rowerr[NS];
__device__ float g_mu[NS];
__device__ float g_mv[NQ];
__device__ float g_m[NS];
__device__ float g_sinv[NS];
__device__ float g_part[(size_t)SPLITK * NS * DD];
__device__ int   g_done;
__device__ int   g_dmax[2];
__device__ int   g_dmaxv[2];
__device__ unsigned g_arrive;
__device__ unsigned g_gen;

// ---------------- MUFU / tf32 helpers ----------------
__device__ __forceinline__ float ex2f(float x) {
    float r; asm("ex2.approx.f32 %0, %1;" : "=f"(r) : "f"(x)); return r;
}
__device__ __forceinline__ float lg2f(float x) {
    float r; asm("lg2.approx.f32 %0, %1;" : "=f"(r) : "f"(x)); return r;
}
__device__ __forceinline__ uint32_t tf32r(float x) {
    uint32_t u; asm("cvt.rna.tf32.f32 %0, %1;" : "=r"(u) : "f"(x)); return u;
}
__device__ __forceinline__ void mma_tf32(float* c,
    uint32_t a0, uint32_t a1, uint32_t a2, uint32_t a3,
    uint32_t b0, uint32_t b1) {
    asm volatile(
        "mma.sync.aligned.m16n8k8.row.col.f32.tf32.tf32.f32 "
        "{%0,%1,%2,%3},{%4,%5,%6,%7},{%8,%9},{%0,%1,%2,%3};\n"
        : "+f"(c[0]), "+f"(c[1]), "+f"(c[2]), "+f"(c[3])
        : "r"(a0), "r"(a1), "r"(a2), "r"(a3), "r"(b0), "r"(b1));
}

// ---------------- software grid barrier (acq_rel, no full membar) ----------------
__device__ __forceinline__ void grid_barrier(unsigned target) {
    __syncthreads();
    if (threadIdx.x == 0) {
        unsigned prev;
        asm volatile("atom.acq_rel.gpu.global.add.u32 %0, [%1], %2;"
                     : "=r"(prev) : "l"(&g_arrive), "r"(1u) : "memory");
        if (prev == GRIDB - 1) {
            g_arrive = 0;
            asm volatile("st.release.gpu.global.u32 [%0], %1;"
                         :: "l"(&g_gen), "r"(target) : "memory");
        } else {
            unsigned g;
            int spins = 0;
            for (;;) {
                asm volatile("ld.acquire.gpu.global.u32 %0, [%1];"
                             : "=r"(g) : "l"(&g_gen) : "memory");
                if (g == target) break;
                if (++spins > 64) __nanosleep(32);
            }
        }
    }
    __syncthreads();
}

// ---------------- init ----------------
__global__ void k_init() {
    int t = blockIdx.x * blockDim.x + threadIdx.x;
    if (t < NS) { g_u[t] = 0.0f; g_mu[t] = 0.0f; }
    if (t < NQ) { g_v[t] = 0.0f; g_mv[t] = 0.0f; }
    if (t == 0) {
        g_done = 0; g_arrive = 0; g_gen = 0;
        g_dmax[0] = 0; g_dmax[1] = 0; g_dmaxv[0] = 0; g_dmaxv[1] = 0;
    }
}

// ---------------- cost matrix via tf32 mma; norms computed in-block ----------------
#define APAD 20
__global__ __launch_bounds__(256) void k_cost(const float* __restrict__ A,
                                              const float* __restrict__ B) {
    __shared__ float Ah[128][APAD], Al[128][APAD];
    __shared__ float Bh[128][APAD], Bl[128][APAD];
    __shared__ float x2s[128], y2s[128];
    int tid = threadIdx.x;
    int lane = tid & 31, wid = tid >> 5;
    int warp_m = (wid & 3) * 32, warp_n = (wid >> 2) * 64;
    int m0 = blockIdx.y * 128, n0 = blockIdx.x * 128;
    int gid = lane >> 2, tig = lane & 3;

    // in-block norms (same lane-strided order as old k_norms -> bit-identical)
    for (int r = 0; r < 16; r++) {
        int row = wid * 16 + r;
        const float* rp = A + (size_t)(m0 + row) * DD;
        float s = 0.0f;
        #pragma unroll
        for (int k = lane; k < DD; k += 32) { float v = rp[k]; s = fmaf(v, v, s); }
        #pragma unroll
        for (int off = 16; off; off >>= 1) s += __shfl_down_sync(0xffffffffu, s, off);
        if (lane == 0) x2s[row] = s;
        const float* cp = B + (size_t)(n0 + row) * DD;
        float t2 = 0.0f;
        #pragma unroll
        for (int k = lane; k < DD; k += 32) { float v = cp[k]; t2 = fmaf(v, v, t2); }
        #pragma unroll
        for (int off = 16; off; off >>= 1) t2 += __shfl_down_sync(0xffffffffu, t2, off);
        if (lane == 0) y2s[row] = t2;
    }
    __syncthreads();

    float acc[2][8][4];
    #pragma unroll
    for (int mi = 0; mi < 2; mi++)
        #pragma unroll
        for (int ni = 0; ni < 8; ni++)
            #pragma unroll
            for (int q = 0; q < 4; q++) acc[mi][ni][q] = 0.0f;

    for (int kk0 = 0; kk0 < DD; kk0 += 16) {
        #pragma unroll
        for (int q = 0; q < 2; q++) {
            int i = tid + q * 256;
            int row = i >> 2, f4 = i & 3;
            float4 a = *reinterpret_cast<const float4*>(A + (size_t)(m0 + row) * DD + kk0 + f4 * 4);
            float4 b = *reinterpret_cast<const float4*>(B + (size_t)(n0 + row) * DD + kk0 + f4 * 4);
            float4 hx, lx;
            hx.x = __uint_as_float(tf32r(a.x)); lx.x = __uint_as_float(tf32r(a.x - hx.x));
            hx.y = __uint_as_float(tf32r(a.y)); lx.y = __uint_as_float(tf32r(a.y - hx.y));
            hx.z = __uint_as_float(tf32r(a.z)); lx.z = __uint_as_float(tf32r(a.z - hx.z));
            hx.w = __uint_as_float(tf32r(a.w)); lx.w = __uint_as_float(tf32r(a.w - hx.w));
            *reinterpret_cast<float4*>(&Ah[row][f4 * 4]) = hx;
            *reinterpret_cast<float4*>(&Al[row][f4 * 4]) = lx;
            hx.x = __uint_as_float(tf32r(b.x)); lx.x = __uint_as_float(tf32r(b.x - hx.x));
            hx.y = __uint_as_float(tf32r(b.y)); lx.y = __uint_as_float(tf32r(b.y - hx.y));
            hx.z = __uint_as_float(tf32r(b.z)); lx.z = __uint_as_float(tf32r(b.z - hx.z));
            hx.w = __uint_as_float(tf32r(b.w)); lx.w = __uint_as_float(tf32r(b.w - hx.w));
            *reinterpret_cast<float4*>(&Bh[row][f4 * 4]) = hx;
            *reinterpret_cast<float4*>(&Bl[row][f4 * 4]) = lx;
        }
        __syncthreads();
        #pragma unroll
        for (int k8 = 0; k8 < 2; k8++) {
            int kc = k8 * 8 + tig;
            uint32_t ah[2][4], al[2][4];
            #pragma unroll
            for (int mi = 0; mi < 2; mi++) {
                int rb = warp_m + mi * 16 + gid;
                ah[mi][0] = __float_as_uint(Ah[rb][kc]);
                ah[mi][1] = __float_as_uint(Ah[rb + 8][kc]);
                ah[mi][2] = __float_as_uint(Ah[rb][kc + 4]);
                ah[mi][3] = __float_as_uint(Ah[rb + 8][kc + 4]);
                al[mi][0] = __float_as_uint(Al[rb][kc]);
                al[mi][1] = __float_as_uint(Al[rb + 8][kc]);
                al[mi][2] = __float_as_uint(Al[rb][kc + 4]);
                al[mi][3] = __float_as_uint(Al[rb + 8][kc + 4]);
            }
            #pragma unroll
            for (int ni = 0; ni < 8; ni++) {
                int nb = warp_n + ni * 8 + gid;
                uint32_t bh0 = __float_as_uint(Bh[nb][kc]);
                uint32_t bh1 = __float_as_uint(Bh[nb][kc + 4]);
                uint32_t bl0 = __float_as_uint(Bl[nb][kc]);
                uint32_t bl1 = __float_as_uint(Bl[nb][kc + 4]);
                #pragma unroll
                for (int mi = 0; mi < 2; mi++) {
                    mma_tf32(acc[mi][ni], ah[mi][0], ah[mi][1], ah[mi][2], ah[mi][3], bh0, bh1);
                    mma_tf32(acc[mi][ni], ah[mi][0], ah[mi][1], ah[mi][2], ah[mi][3], bl0, bl1);
                    mma_tf32(acc[mi][ni], al[mi][0], al[mi][1], al[mi][2], al[mi][3], bh0, bh1);
                }
            }
        }
        __syncthreads();
    }
    #pragma unroll
    for (int mi = 0; mi < 2; mi++) {
        int rl = warp_m + mi * 16 + gid;
        int r0 = m0 + rl;
        float x2a = x2s[rl], x2b = x2s[rl + 8];
        #pragma unroll
        for (int ni = 0; ni < 8; ni++) {
            int cl = warp_n + ni * 8 + 2 * tig;
            int c0 = n0 + cl;
            float y20 = y2s[cl], y21 = y2s[cl + 1];
            float2 w0 = { x2a + y20 - 2.0f * acc[mi][ni][0],
                          x2a + y21 - 2.0f * acc[mi][ni][1] };
            float2 w1 = { x2b + y20 - 2.0f * acc[mi][ni][2],
                          x2b + y21 - 2.0f * acc[mi][ni][3] };
            *reinterpret_cast<float2*>(g_C + (size_t)r0 * NQ + c0) = w0;
            *reinterpret_cast<float2*>(g_C + (size_t)(r0 + 8) * NQ + c0) = w1;
        }
    }
}

// ---------------- persistent Sinkhorn loop + fused stats epilogue ----------------
extern __shared__ float s_cache[];   // 2 * NQ floats (rows i0, i0+1)

__global__ __launch_bounds__(TPB, 2) void k_sink() {
    __shared__ float mrow[4][17];
    __shared__ float ssum[4][17];
    __shared__ float smv[64][33];
    __shared__ float ssv[64][33];
    __shared__ float smM[32];
    __shared__ float u2s[NS];
    __shared__ float sered[16];

    int tid  = threadIdx.x, bid = blockIdx.x;
    int lane = tid & 31,    w   = tid >> 5;
    unsigned bargen = 0;
    bool done = false;
    int i0 = bid * 4;
    const float* C0 = g_C + (size_t)i0 * NQ;

    #pragma unroll
    for (int t = 0; t < (2 * NQ / 4) / TPB; t++) {
        int idx = tid + t * TPB;
        reinterpret_cast<float4*>(s_cache)[idx] =
            reinterpret_cast<const float4*>(C0)[idx];
    }
    __syncthreads();

    for (int it = 0; it < MAX_ITER; it++) {
        if (done) break;
        int par = it & 1;

        float dmv2 = __int_as_float(g_dmaxv[1 - par]);
        bool onepass_u = (it > 0) && (dmv2 <= 20.0f);

        if (onepass_u) {
            float me2_0 = fmaf(g_mu[i0+0], K2, dmv2);
            float me2_1 = fmaf(g_mu[i0+1], K2, dmv2);
            float me2_2 = fmaf(g_mu[i0+2], K2, dmv2);
            float me2_3 = fmaf(g_mu[i0+3], K2, dmv2);
            float mx[4] = {-1e30f, -1e30f, -1e30f, -1e30f};
            float ss[4] = {0, 0, 0, 0};
            #pragma unroll
            for (int k = 0; k < 4; k++) {
                int off = tid * 4 + k * 2048;
                float4 vv = *reinterpret_cast<const float4*>(g_v + off);
                float4 c0 = *reinterpret_cast<const float4*>(s_cache + off);
                float4 c1 = *reinterpret_cast<const float4*>(s_cache + NQ + off);
                float4 c2 = *reinterpret_cast<const float4*>(C0 + 2 * NQ + off);
                float4 c3 = *reinterpret_cast<const float4*>(C0 + 3 * NQ + off);
                {
                    float a0 = vv.x - c0.x, a1 = vv.y - c0.y, a2 = vv.z - c0.z, a3 = vv.w - c0.w;
                    mx[0] = fmaxf(mx[0], fmaxf(fmaxf(a0, a1), fmaxf(a2, a3)));
                    ss[0] += (ex2f(fmaf(a0, K2, -me2_0)) + ex2f(fmaf(a1, K2, -me2_0)))
                           + (ex2f(fmaf(a2, K2, -me2_0)) + ex2f(fmaf(a3, K2, -me2_0)));
                }
                {
                    float a0 = vv.x - c1.x, a1 = vv.y - c1.y, a2 = vv.z - c1.z, a3 = vv.w - c1.w;
                    mx[1] = fmaxf(mx[1], fmaxf(fmaxf(a0, a1), fmaxf(a2, a3)));
                    ss[1] += (ex2f(fmaf(a0, K2, -me2_1)) + ex2f(fmaf(a1, K2, -me2_1)))
                           + (ex2f(fmaf(a2, K2, -me2_1)) + ex2f(fmaf(a3, K2, -me2_1)));
                }
                {
                    float a0 = vv.x - c2.x, a1 = vv.y - c2.y, a2 = vv.z - c2.z, a3 = vv.w - c2.w;
                    mx[2] = fmaxf(mx[2], fmaxf(fmaxf(a0, a1), fmaxf(a2, a3)));
                    ss[2] += (ex2f(fmaf(a0, K2, -me2_2)) + ex2f(fmaf(a1, K2, -me2_2)))
                           + (ex2f(fmaf(a2, K2, -me2_2)) + ex2f(fmaf(a3, K2, -me2_2)));
                }
                {
                    float a0 = vv.x - c3.x, a1 = vv.y - c3.y, a2 = vv.z - c3.z, a3 = vv.w - c3.w;
                    mx[3] = fmaxf(mx[3], fmaxf(fmaxf(a0, a1), fmaxf(a2, a3)));
                    ss[3] += (ex2f(fmaf(a0, K2, -me2_3)) + ex2f(fmaf(a1, K2, -me2_3)))
                           + (ex2f(fmaf(a2, K2, -me2_3)) + ex2f(fmaf(a3, K2, -me2_3)));
                }
            }
            #pragma unroll
            for (int r = 0; r < 4; r++) {
                float m = mx[r], s = ss[r];
                #pragma unroll
                for (int off = 16; off; off >>= 1) {
                    m = fmaxf(m, __shfl_xor_sync(0xffffffffu, m, off));
                    s += __shfl_xor_sync(0xffffffffu, s, off);
                }
                if (lane == 0) { mrow[r][w] = m; ssum[r][w] = s; }
            }
            __syncthreads();
            float delta2 = 0.0f;
            if (tid < 4) {
                int i = i0 + tid;
                float me2 = fmaf(g_mu[i], K2, dmv2);
                float mr = mrow[tid][0];
                float S  = ssum[tid][0];
                #pragma unroll
                for (int q = 1; q < 16; q++) { mr = fmaxf(mr, mrow[tid][q]); S += ssum[tid][q]; }
                float L    = LN2 * (me2 + lg2f(S));
                float unew = EPSR * (LOG_MU - L);
                float d    = fabsf(unew - g_u[i]);
                g_rowerr[i] = d;
                g_u[i]  = unew;
                g_mu[i] = mr;
                delta2 = d * K2;
            }
            if (w == 0) {
                #pragma unroll
                for (int off = 16; off; off >>= 1)
                    delta2 = fmaxf(delta2, __shfl_xor_sync(0xffffffffu, delta2, off));
                if (lane == 0) atomicMax(&g_dmax[par], __float_as_int(delta2));
            }
        } else {
            float mx[4] = {-1e30f, -1e30f, -1e30f, -1e30f};
            #pragma unroll
            for (int k = 0; k < 4; k++) {
                int off = tid * 4 + k * 2048;
                float4 vv = *reinterpret_cast<const float4*>(g_v + off);
                float4 c0 = *reinterpret_cast<const float4*>(s_cache + off);
                float4 c1 = *reinterpret_cast<const float4*>(s_cache + NQ + off);
                float4 c2 = *reinterpret_cast<const float4*>(C0 + 2 * NQ + off);
                float4 c3 = *reinterpret_cast<const float4*>(C0 + 3 * NQ + off);
                mx[0] = fmaxf(mx[0], fmaxf(fmaxf(vv.x - c0.x, vv.y - c0.y),
                                           fmaxf(vv.z - c0.z, vv.w - c0.w)));
                mx[1] = fmaxf(mx[1], fmaxf(fmaxf(vv.x - c1.x, vv.y - c1.y),
                                           fmaxf(vv.z - c1.z, vv.w - c1.w)));
                mx[2] = fmaxf(mx[2], fmaxf(fmaxf(vv.x - c2.x, vv.y - c2.y),
                                           fmaxf(vv.z - c2.z, vv.w - c2.w)));
                mx[3] = fmaxf(mx[3], fmaxf(fmaxf(vv.x - c3.x, vv.y - c3.y),
                                           fmaxf(vv.z - c3.z, vv.w - c3.w)));
            }
            #pragma unroll
            for (int r = 0; r < 4; r++) {
                float m = mx[r];
                #pragma unroll
                for (int off = 16; off; off >>= 1)
                    m = fmaxf(m, __shfl_xor_sync(0xffffffffu, m, off));
                if (lane == 0) mrow[r][w] = m;
            }
            __syncthreads();
            float rm2[4];
            #pragma unroll
            for (int r = 0; r < 4; r++) {
                float mr = mrow[r][0];
                #pragma unroll
                for (int q = 1; q < 16; q++) mr = fmaxf(mr, mrow[r][q]);
                rm2[r] = mr * K2;
                if (tid == r) g_mu[i0 + r] = mr;
            }
            float ss[4] = {0, 0, 0, 0};
            #pragma unroll
            for (int k = 0; k < 4; k++) {
                int off = tid * 4 + k * 2048;
                float4 vv = *reinterpret_cast<const float4*>(g_v + off);
                float4 c0 = *reinterpret_cast<const float4*>(s_cache + off);
                float4 c1 = *reinterpret_cast<const float4*>(s_cache + NQ + off);
                float4 c2 = *reinterpret_cast<const float4*>(C0 + 2 * NQ + off);
                float4 c3 = *reinterpret_cast<const float4*>(C0 + 3 * NQ + off);
                ss[0] += (ex2f(fmaf(vv.x - c0.x, K2, -rm2[0])) + ex2f(fmaf(vv.y - c0.y, K2, -rm2[0])))
                       + (ex2f(fmaf(vv.z - c0.z, K2, -rm2[0])) + ex2f(fmaf(vv.w - c0.w, K2, -rm2[0])));
                ss[1] += (ex2f(fmaf(vv.x - c1.x, K2, -rm2[1])) + ex2f(fmaf(vv.y - c1.y, K2, -rm2[1])))
                       + (ex2f(fmaf(vv.z - c1.z, K2, -rm2[1])) + ex2f(fmaf(vv.w - c1.w, K2, -rm2[1])));
                ss[2] += (ex2f(fmaf(vv.x - c2.x, K2, -rm2[2])) + ex2f(fmaf(vv.y - c2.y, K2, -rm2[2])))
                       + (ex2f(fmaf(vv.z - c2.z, K2, -rm2[2])) + ex2f(fmaf(vv.w - c2.w, K2, -rm2[2])));
                ss[3] += (ex2f(fmaf(vv.x - c3.x, K2, -rm2[3])) + ex2f(fmaf(vv.y - c3.y, K2, -rm2[3])))
                       + (ex2f(fmaf(vv.z - c3.z, K2, -rm2[3])) + ex2f(fmaf(vv.w - c3.w, K2, -rm2[3])));
            }
            #pragma unroll
            for (int r = 0; r < 4; r++) {
                float s = ss[r];
                #pragma unroll
                for (int off = 16; off; off >>= 1)
                    s += __shfl_xor_sync(0xffffffffu, s, off);
                if (lane == 0) ssum[r][w] = s;
            }
            __syncthreads();
            float delta2 = 0.0f;
            if (tid < 4) {
                int i = i0 + tid;
                float S = ssum[tid][0];
                #pragma unroll
                for (int q = 1; q < 16; q++) S += ssum[tid][q];
                float L    = LN2 * (rm2[tid] + lg2f(S));
                float unew = EPSR * (LOG_MU - L);
                float d    = fabsf(unew - g_u[i]);
                g_rowerr[i] = d;
                g_u[i] = unew;
                delta2 = d * K2;
            }
            if (w == 0) {
                #pragma unroll
                for (int off = 16; off; off >>= 1)
                    delta2 = fmaxf(delta2, __shfl_xor_sync(0xffffffffu, delta2, off));
                if (lane == 0) atomicMax(&g_dmax[par], __float_as_int(delta2));
            }
        }

        grid_barrier(++bargen);

        {
            u2s[tid]       = g_u[tid]       * K2;
            u2s[tid + TPB] = g_u[tid + TPB] * K2;
            if (bid == 0 && tid == 0) { g_dmax[1 - par] = 0; g_dmaxv[1 - par] = 0; }
            __syncthreads();

            float dmaxu2 = __int_as_float(g_dmax[par]);
            bool onepass = (it > 0) && (dmaxu2 <= 40.0f);

            int cg = tid & 7;
            int rg = tid >> 3;
            int jc = bid * 32 + cg * 4;
            const float* Cp = g_C + jc;
            int ib = rg * 16;

            if (onepass) {
                float4 mvp = *reinterpret_cast<const float4*>(g_mv + jc);
                float me0 = mvp.x + dmaxu2, me1 = mvp.y + dmaxu2;
                float me2 = mvp.z + dmaxu2, me3 = mvp.w + dmaxu2;
                float mx0 = -1e30f, mx1 = -1e30f, mx2 = -1e30f, mx3 = -1e30f;
                float s0 = 0, s1 = 0, s2 = 0, s3 = 0;
                #pragma unroll
                for (int ii = 0; ii < 16; ii++) {
                    int i = ib + ii;
                    float4 c = *reinterpret_cast<const float4*>(Cp + (size_t)i * NQ);
                    float u2 = u2s[i];
                    float a0 = fmaf(c.x, -K2, u2);
                    float a1 = fmaf(c.y, -K2, u2);
                    float a2 = fmaf(c.z, -K2, u2);
                    float a3 = fmaf(c.w, -K2, u2);
                    mx0 = fmaxf(mx0, a0); s0 += ex2f(a0 - me0);
                    mx1 = fmaxf(mx1, a1); s1 += ex2f(a1 - me1);
                    mx2 = fmaxf(mx2, a2); s2 += ex2f(a2 - me2);
                    mx3 = fmaxf(mx3, a3); s3 += ex2f(a3 - me3);
                }
                int cb = cg * 4;
                smv[rg][cb+0] = mx0; ssv[rg][cb+0] = s0;
                smv[rg][cb+1] = mx1; ssv[rg][cb+1] = s1;
                smv[rg][cb+2] = mx2; ssv[rg][cb+2] = s2;
                smv[rg][cb+3] = mx3; ssv[rg][cb+3] = s3;
                __syncthreads();
                // parallel tail: 8 threads per column (tid<256), width-8 shuffle tree
                float dv2 = 0.0f;
                if (tid < 256) {
                    int j8 = tid >> 3;      // column 0..31
                    int q8 = tid & 7;       // row-group slice
                    float M = smv[q8 * 8][j8], S = ssv[q8 * 8][j8];
                    #pragma unroll
                    for (int q = 1; q < 8; q++) {
                        M = fmaxf(M, smv[q8 * 8 + q][j8]);
                        S += ssv[q8 * 8 + q][j8];
                    }
                    #pragma unroll
                    for (int off = 4; off; off >>= 1) {
                        M = fmaxf(M, __shfl_down_sync(0xffffffffu, M, off));
                        S += __shfl_down_sync(0xffffffffu, S, off);
                    }
                    if (q8 == 0) {
                        int j = bid * 32 + j8;
                        float m_est = g_mv[j] + dmaxu2;
                        g_mv[j] = M;
                        float vold = g_v[j];
                        float vnew = EPSR * (LOG_NU - LN2 * (m_est + lg2f(S)));
                        g_v[j] = vnew;
                        dv2 = fabsf(vnew - vold) * K2;
                    }
                }
                if (w < 8) {
                    #pragma unroll
                    for (int off = 16; off; off >>= 1)
                        dv2 = fmaxf(dv2, __shfl_xor_sync(0xffffffffu, dv2, off));
                    if (lane == 0) atomicMax(&g_dmaxv[par], __float_as_int(dv2));
                }
            } else {
                float mx0 = -1e30f, mx1 = -1e30f, mx2 = -1e30f, mx3 = -1e30f;
                #pragma unroll
                for (int ii = 0; ii < 16; ii++) {
                    int i = ib + ii;
                    float4 c = *reinterpret_cast<const float4*>(Cp + (size_t)i * NQ);
                    float u2 = u2s[i];
                    mx0 = fmaxf(mx0, fmaf(c.x, -K2, u2));
                    mx1 = fmaxf(mx1, fmaf(c.y, -K2, u2));
                    mx2 = fmaxf(mx2, fmaf(c.z, -K2, u2));
                    mx3 = fmaxf(mx3, fmaf(c.w, -K2, u2));
                }
                int cb = cg * 4;
                smv[rg][cb+0] = mx0; smv[rg][cb+1] = mx1;
                smv[rg][cb+2] = mx2; smv[rg][cb+3] = mx3;
                __syncthreads();
                if (tid < 256) {
                    int j8 = tid >> 3, q8 = tid & 7;
                    float M = smv[q8 * 8][j8];
                    #pragma unroll
                    for (int q = 1; q < 8; q++) M = fmaxf(M, smv[q8 * 8 + q][j8]);
                    #pragma unroll
                    for (int off = 4; off; off >>= 1)
                        M = fmaxf(M, __shfl_down_sync(0xffffffffu, M, off));
                    if (q8 == 0) smM[j8] = M;
                }
                __syncthreads();
                float M0 = smM[cb+0], M1 = smM[cb+1], M2 = smM[cb+2], M3 = smM[cb+3];
                float s0 = 0, s1 = 0, s2 = 0, s3 = 0;
                #pragma unroll
                for (int ii = 0; ii < 16; ii++) {
                    int i = ib + ii;
                    float4 c = *reinterpret_cast<const float4*>(Cp + (size_t)i * NQ);
                    float u2 = u2s[i];
                    s0 += ex2f(fmaf(c.x, -K2, u2) - M0);
                    s1 += ex2f(fmaf(c.y, -K2, u2) - M1);
                    s2 += ex2f(fmaf(c.z, -K2, u2) - M2);
                    s3 += ex2f(fmaf(c.w, -K2, u2) - M3);
                }
                ssv[rg][cb+0] = s0; ssv[rg][cb+1] = s1;
                ssv[rg][cb+2] = s2; ssv[rg][cb+3] = s3;
                __syncthreads();
                float dv2 = 0.0f;
                if (tid < 256) {
                    int j8 = tid >> 3, q8 = tid & 7;
                    float S = ssv[q8 * 8][j8];
                    #pragma unroll
                    for (int q = 1; q < 8; q++) S += ssv[q8 * 8 + q][j8];
                    #pragma unroll
                    for (int off = 4; off; off >>= 1)
                        S += __shfl_down_sync(0xffffffffu, S, off);
                    if (q8 == 0) {
                        int j = bid * 32 + j8;
                        float M = smM[j8];
                        g_mv[j] = M;
                        float vold = g_v[j];
                        float vnew = EPSR * (LOG_NU - LN2 * (M + lg2f(S)));
                        g_v[j] = vnew;
                        dv2 = fabsf(vnew - vold) * K2;
                    }
                }
                if (w < 8) {
                    #pragma unroll
                    for (int off = 16; off; off >>= 1)
                        dv2 = fmaxf(dv2, __shfl_xor_sync(0xffffffffu, dv2, off));
                    if (lane == 0) atomicMax(&g_dmaxv[par], __float_as_int(dv2));
                }
            }

            if (bid == 0) {
                float e = g_rowerr[tid] + g_rowerr[tid + TPB];
                #pragma unroll
                for (int off = 16; off; off >>= 1)
                    e += __shfl_down_sync(0xffffffffu, e, off);
                if (lane == 0) sered[w] = e;
                __syncthreads();
                if (tid == 0) {
                    float E = 0;
                    #pragma unroll
                    for (int q = 0; q < 16; q++) E += sered[q];
                    if (E < THRESHV) g_done = 1;
                }
            }
        }

        grid_barrier(++bargen);
        done = (*(volatile int*)&g_done) != 0;
    }

    // fused stats epilogue (exact, final v; rows 0,1 from smem)
    {
        float mx[4] = {-1e30f, -1e30f, -1e30f, -1e30f};
        #pragma unroll
        for (int k = 0; k < 4; k++) {
            int off = tid * 4 + k * 2048;
            float4 vv = *reinterpret_cast<const float4*>(g_v + off);
            float4 c0 = *reinterpret_cast<const float4*>(s_cache + off);
            float4 c1 = *reinterpret_cast<const float4*>(s_cache + NQ + off);
            float4 c2 = *reinterpret_cast<const float4*>(C0 + 2 * NQ + off);
            float4 c3 = *reinterpret_cast<const float4*>(C0 + 3 * NQ + off);
            mx[0] = fmaxf(mx[0], fmaxf(fmaxf(vv.x - c0.x, vv.y - c0.y),
                                       fmaxf(vv.z - c0.z, vv.w - c0.w)));
            mx[1] = fmaxf(mx[1], fmaxf(fmaxf(vv.x - c1.x, vv.y - c1.y),
                                       fmaxf(vv.z - c1.z, vv.w - c1.w)));
            mx[2] = fmaxf(mx[2], fmaxf(fmaxf(vv.x - c2.x, vv.y - c2.y),
                                       fmaxf(vv.z - c2.z, vv.w - c2.w)));
            mx[3] = fmaxf(mx[3], fmaxf(fmaxf(vv.x - c3.x, vv.y - c3.y),
                                       fmaxf(vv.z - c3.z, vv.w - c3.w)));
        }
        #pragma unroll
        for (int r = 0; r < 4; r++) {
            float m = mx[r];
            #pragma unroll
            for (int off = 16; off; off >>= 1)
                m = fmaxf(m, __shfl_xor_sync(0xffffffffu, m, off));
            if (lane == 0) mrow[r][w] = m;
        }
        __syncthreads();
        float rm2[4];
        #pragma unroll
        for (int r = 0; r < 4; r++) {
            float mr = mrow[r][0];
            #pragma unroll
            for (int q = 1; q < 16; q++) mr = fmaxf(mr, mrow[r][q]);
            rm2[r] = mr * K2;
        }
        float ss[4] = {0, 0, 0, 0};
        #pragma unroll
        for (int k = 0; k < 4; k++) {
            int off = tid * 4 + k * 2048;
            float4 vv = *reinterpret_cast<const float4*>(g_v + off);
            float4 c0 = *reinterpret_cast<const float4*>(s_cache + off);
            float4 c1 = *reinterpret_cast<const float4*>(s_cache + NQ + off);
            float4 c2 = *reinterpret_cast<const float4*>(C0 + 2 * NQ + off);
            float4 c3 = *reinterpret_cast<const float4*>(C0 + 3 * NQ + off);
            ss[0] += (ex2f(fmaf(vv.x - c0.x, K2, -rm2[0])) + ex2f(fmaf(vv.y - c0.y, K2, -rm2[0])))
                   + (ex2f(fmaf(vv.z - c0.z, K2, -rm2[0])) + ex2f(fmaf(vv.w - c0.w, K2, -rm2[0])));
            ss[1] += (ex2f(fmaf(vv.x - c1.x, K2, -rm2[1])) + ex2f(fmaf(vv.y - c1.y, K2, -rm2[1])))
                   + (ex2f(fmaf(vv.z - c1.z, K2, -rm2[1])) + ex2f(fmaf(vv.w - c1.w, K2, -rm2[1])));
            ss[2] += (ex2f(fmaf(vv.x - c2.x, K2, -rm2[2])) + ex2f(fmaf(vv.y - c2.y, K2, -rm2[2])))
                   + (ex2f(fmaf(vv.z - c2.z, K2, -rm2[2])) + ex2f(fmaf(vv.w - c2.w, K2, -rm2[2])));
            ss[3] += (ex2f(fmaf(vv.x - c3.x, K2, -rm2[3])) + ex2f(fmaf(vv.y - c3.y, K2, -rm2[3])))
                   + (ex2f(fmaf(vv.z - c3.z, K2, -rm2[3])) + ex2f(fmaf(vv.w - c3.w, K2, -rm2[3])));
        }
        #pragma unroll
        for (int r = 0; r < 4; r++) {
            float s = ss[r];
            #pragma unroll
            for (int off = 16; off; off >>= 1)
                s += __shfl_xor_sync(0xffffffffu, s, off);
            if (lane == 0) ssum[r][w] = s;
        }
        __syncthreads();
        if (tid < 4) {
            int i = i0 + tid;
            float S = ssum[tid][0];
            #pragma unroll
            for (int q = 1; q < 16; q++) S += ssum[tid][q];
            g_m[i]    = rm2[tid];
            g_sinv[i] = 1.0f / S;
        }
    }
}

// ---------------- out = unnormalized-softmax(C) @ zq via tf32 mma (sinv in reduce) ----------------
#define BPAD 132
__global__ __launch_bounds__(256) void k_out(const float* __restrict__ B) {
    __shared__ float Ah[128][APAD], Al[128][APAD];
    __shared__ float Bh[16][BPAD], Bl[16][BPAD];
    int tid = threadIdx.x;
    int lane = tid & 31, wid = tid >> 5;
    int warp_m = (wid & 3) * 32, warp_n = (wid >> 2) * 64;
    int m0 = blockIdx.y * 128, n0 = blockIdx.x * 128;
    int kbase = blockIdx.z * (NQ / SPLITK);
    int gid = lane >> 2, tig = lane & 3;

    float acc[2][8][4];
    #pragma unroll
    for (int mi = 0; mi < 2; mi++)
        #pragma unroll
        for (int ni = 0; ni < 8; ni++)
            #pragma unroll
            for (int q = 0; q < 4; q++) acc[mi][ni][q] = 0.0f;

    for (int kk0 = kbase; kk0 < kbase + NQ / SPLITK; kk0 += 16) {
        #pragma unroll
        for (int q = 0; q < 2; q++) {
            int i = tid + q * 256;
            int row = i >> 2, f4 = i & 3;
            int grow = m0 + row;
            float mi2 = g_m[grow];
            float4 c  = *reinterpret_cast<const float4*>(g_C + (size_t)grow * NQ + kk0 + f4 * 4);
            float4 vv = *reinterpret_cast<const float4*>(g_v + kk0 + f4 * 4);
            float4 wv;
            wv.x = ex2f(fmaf(vv.x - c.x, K2, -mi2));
            wv.y = ex2f(fmaf(vv.y - c.y, K2, -mi2));
            wv.z = ex2f(fmaf(vv.z - c.z, K2, -mi2));
            wv.w = ex2f(fmaf(vv.w - c.w, K2, -mi2));
            float4 hx, lx;
            hx.x = __uint_as_float(tf32r(wv.x)); lx.x = __uint_as_float(tf32r(wv.x - hx.x));
            hx.y = __uint_as_float(tf32r(wv.y)); lx.y = __uint_as_float(tf32r(wv.y - hx.y));
            hx.z = __uint_as_float(tf32r(wv.z)); lx.z = __uint_as_float(tf32r(wv.z - hx.z));
            hx.w = __uint_as_float(tf32r(wv.w)); lx.w = __uint_as_float(tf32r(wv.w - hx.w));
            *reinterpret_cast<float4*>(&Ah[row][f4 * 4]) = hx;
            *reinterpret_cast<float4*>(&Al[row][f4 * 4]) = lx;
        }
        #pragma unroll
        for (int q = 0; q < 2; q++) {
            int i = tid + q * 256;
            int krow = i >> 5, f4c = i & 31;
            float4 b = *reinterpret_cast<const float4*>(B + (size_t)(kk0 + krow) * DD + n0 + f4c * 4);
            float4 hx, lx;
            hx.x = __uint_as_float(tf32r(b.x)); lx.x = __uint_as_float(tf32r(b.x - hx.x));
            hx.y = __uint_as_float(tf32r(b.y)); lx.y = __uint_as_float(tf32r(b.y - hx.y));
            hx.z = __uint_as_float(tf32r(b.z)); lx.z = __uint_as_float(tf32r(b.z - hx.z));
            hx.w = __uint_as_float(tf32r(b.w)); lx.w = __uint_as_float(tf32r(b.w - hx.w));
            *reinterpret_cast<float4*>(&Bh[krow][f4c * 4]) = hx;
            *reinterpret_cast<float4*>(&Bl[krow][f4c * 4]) = lx;
        }
        __syncthreads();
        #pragma unroll
        for (int k8 = 0; k8 < 2; k8++) {
            int kc = k8 * 8 + tig;
            uint32_t ah[2][4], al[2][4];
            #pragma unroll
            for (int mi = 0; mi < 2; mi++) {
                int rb = warp_m + mi * 16 + gid;
                ah[mi][0] = __float_as_uint(Ah[rb][kc]);
                ah[mi][1] = __float_as_uint(Ah[rb + 8][kc]);
                ah[mi][2] = __float_as_uint(Ah[rb][kc + 4]);
                ah[mi][3] = __float_as_uint(Ah[rb + 8][kc + 4]);
                al[mi][0] = __float_as_uint(Al[rb][kc]);
                al[mi][1] = __float_as_uint(Al[rb + 8][kc]);
                al[mi][2] = __float_as_uint(Al[rb][kc + 4]);
                al[mi][3] = __float_as_uint(Al[rb + 8][kc + 4]);
            }
            #pragma unroll
            for (int ni = 0; ni < 8; ni++) {
                int nb = warp_n + ni * 8 + gid;
                uint32_t bh0 = __float_as_uint(Bh[k8 * 8 + tig][nb]);
                uint32_t bh1 = __float_as_uint(Bh[k8 * 8 + tig + 4][nb]);
                uint32_t bl0 = __float_as_uint(Bl[k8 * 8 + tig][nb]);
                uint32_t bl1 = __float_as_uint(Bl[k8 * 8 + tig + 4][nb]);
                #pragma unroll
                for (int mi = 0; mi < 2; mi++) {
                    mma_tf32(acc[mi][ni], ah[mi][0], ah[mi][1], ah[mi][2], ah[mi][3], bh0, bh1);
                    mma_tf32(acc[mi][ni], ah[mi][0], ah[mi][1], ah[mi][2], ah[mi][3], bl0, bl1);
                    mma_tf32(acc[mi][ni], al[mi][0], al[mi][1], al[mi][2], al[mi][3], bh0, bh1);
                }
            }
        }
        __syncthreads();
    }
    float* P = g_part + (size_t)blockIdx.z * NS * DD;
    #pragma unroll
    for (int mi = 0; mi < 2; mi++) {
        int r0 = m0 + warp_m + mi * 16 + gid;
        #pragma unroll
        for (int ni = 0; ni < 8; ni++) {
            int c0 = n0 + warp_n + ni * 8 + 2 * tig;
            float2 w0 = { acc[mi][ni][0], acc[mi][ni][1] };
            float2 w1 = { acc[mi][ni][2], acc[mi][ni][3] };
            *reinterpret_cast<float2*>(P + (size_t)r0 * DD + c0) = w0;
            *reinterpret_cast<float2*>(P + (size_t)(r0 + 8) * DD + c0) = w1;
        }
    }
}

// ---------------- fused: reduce split-K + normalize, and copy z_query ----------------
#define RED_BLOCKS (NS * DD / 256)                 // 1024
#define CPY_BLOCKS (NQ * DD / 4 / 256)             // 2048
__global__ void k_finish(const float* __restrict__ zq, float* __restrict__ out) {
    int b = blockIdx.x;
    if (b < RED_BLOCKS) {
        int t = b * blockDim.x + threadIdx.x;
        float s = 0.0f;
        #pragma unroll
        for (int q = 0; q < SPLITK; q++) s += g_part[(size_t)q * NS * DD + t];
        out[t] = s * g_sinv[t >> 8];
    } else {
        int t = (b - RED_BLOCKS) * blockDim.x + threadIdx.x;
        reinterpret_cast<float4*>(out + NS * DD)[t] =
            reinterpret_cast<const float4*>(zq)[t];
    }
}

// ---------------- launch ----------------
extern "C" void kernel_launch(void* const* d_in, const int* in_sizes, int n_in,
                              void* d_out, int out_size) {
    const float* zs = (const float*)d_in[0];
    const float* zq = (const float*)d_in[1];
    if (n_in >= 2 && in_sizes[0] == NQ * DD) {
        const float* t = zs; zs = zq; zq = t;
    }
    float* out = (float*)d_out;

    cudaFuncSetAttribute(k_sink, cudaFuncAttributeMaxDynamicSharedMemorySize,
                         2 * NQ * (int)sizeof(float));

    k_init<<<(NQ + 255) / 256, 256>>>();
    k_cost<<<dim3(NQ / 128, NS / 128), 256>>>(zs, zq);
    k_sink<<<GRIDB, TPB, 2 * NQ * sizeof(float)>>>();
    k_out<<<dim3(DD / 128, NS / 128, SPLITK), 256>>>(zq);
    k_finish<<<RED_BLOCKS + CPY_BLOCKS, 256>>>(zq, out);
}